// round 6
// baseline (speedup 1.0000x reference)
#include <cuda_runtime.h>
#include <cuda_fp16.h>

// ---------------------------------------------------------------------------
// HybridForecaster: SNN(LIF) -> GRU -> linear head
// B=64, T=2048, C=64, H=256, HOR=96, BETA=0.9, THR=1.0
//
// K1 cur_gemm : cur[bt,h] = x[bt,:].snn_w[h,:] + snn_b[h]          [BT,256]
// K2 lif      : per-(b,h) membrane recurrence over t -> spikes     [BT,256]
// K3 gx_gemm  : gx[bt,g] = [x|spk][bt,:].gru_wih[g,:] + gru_bih[g] [BT,768]
// K4 gru      : persistent cluster(2)-per-batch scan; whh fp16 in smem,
//               per-step h exchange via DSMEM + barrier.cluster
// K5 head     : out[b,o] = hT[b,:].head_w[o,:] + head_b[o]         [64,96]
// ---------------------------------------------------------------------------

#define Bb   64
#define Tt   2048
#define Cc   64
#define Hh   256
#define G3   768
#define HORd 96
#define BT   (Bb * Tt)

// scratch (device globals — no allocation allowed)
__device__ float g_cur[(size_t)BT * Hh];   // 134 MB
__device__ float g_spk[(size_t)BT * Hh];   // 134 MB
__device__ float g_gx [(size_t)BT * G3];   // 402 MB
__device__ float g_hT [Bb * Hh];

// ---------------------------------------------------------------------------
// K1: cur = x @ snn_w^T + snn_b   (M=BT, N=256, K=64). BM=128 BN=64 BK=32.
// 256 threads, 8x4 register tile. Conflict-free strided smem reads.
// ---------------------------------------------------------------------------
__global__ __launch_bounds__(256) void cur_gemm_kernel(
    const float* __restrict__ x, const float* __restrict__ w,
    const float* __restrict__ bias) {
  __shared__ float As[32][130];
  __shared__ float Bs[32][66];
  const int row0 = blockIdx.x * 128;
  const int col0 = blockIdx.y * 64;
  const int tid  = threadIdx.x;
  const int tm   = tid & 15;   // rows tm + 16*i
  const int tn   = tid >> 4;   // cols tn*4 + j
  float acc[8][4];
#pragma unroll
  for (int i = 0; i < 8; i++)
#pragma unroll
    for (int j = 0; j < 4; j++) acc[i][j] = 0.f;

  const int lm = tid >> 3;          // 0..31
  const int lk = (tid & 7) << 2;    // 0,4,...,28

  for (int k0 = 0; k0 < 64; k0 += 32) {
#pragma unroll
    for (int i = 0; i < 4; i++) {
      int m = lm + 32 * i;
      float4 v = *reinterpret_cast<const float4*>(
          &x[(size_t)(row0 + m) * Cc + k0 + lk]);
      As[lk + 0][m] = v.x; As[lk + 1][m] = v.y;
      As[lk + 2][m] = v.z; As[lk + 3][m] = v.w;
    }
#pragma unroll
    for (int i = 0; i < 2; i++) {
      int n = lm + 32 * i;
      float4 v = *reinterpret_cast<const float4*>(
          &w[(size_t)(col0 + n) * Cc + k0 + lk]);
      Bs[lk + 0][n] = v.x; Bs[lk + 1][n] = v.y;
      Bs[lk + 2][n] = v.z; Bs[lk + 3][n] = v.w;
    }
    __syncthreads();
#pragma unroll
    for (int kk = 0; kk < 32; kk++) {
      float a[8], b[4];
#pragma unroll
      for (int i = 0; i < 8; i++) a[i] = As[kk][tm + 16 * i];
#pragma unroll
      for (int j = 0; j < 4; j++) b[j] = Bs[kk][tn * 4 + j];
#pragma unroll
      for (int i = 0; i < 8; i++)
#pragma unroll
        for (int j = 0; j < 4; j++) acc[i][j] += a[i] * b[j];
    }
    __syncthreads();
  }
  float4 bv = *reinterpret_cast<const float4*>(&bias[col0 + tn * 4]);
#pragma unroll
  for (int i = 0; i < 8; i++) {
    float4 o;
    o.x = acc[i][0] + bv.x; o.y = acc[i][1] + bv.y;
    o.z = acc[i][2] + bv.z; o.w = acc[i][3] + bv.w;
    *reinterpret_cast<float4*>(
        &g_cur[(size_t)(row0 + tm + 16 * i) * Hh + col0 + tn * 4]) = o;
  }
}

// ---------------------------------------------------------------------------
// K2: LIF scan. thread = (b,h). 16-deep load unroll for MLP.
//   reset = (mem > 1);  mem = 0.9*mem + cur - reset;  spk = (mem > 1)
// ---------------------------------------------------------------------------
__global__ __launch_bounds__(256) void lif_kernel() {
  const int b = blockIdx.x;
  const int h = threadIdx.x;
  const float* cp = g_cur + (size_t)b * Tt * Hh + h;
  float* sp = g_spk + (size_t)b * Tt * Hh + h;
  float mem = 0.f;
#pragma unroll 1
  for (int t = 0; t < Tt; t += 16) {
    float v[16];
#pragma unroll
    for (int i = 0; i < 16; i++) v[i] = __ldcs(cp + (size_t)(t + i) * Hh);
#pragma unroll
    for (int i = 0; i < 16; i++) {
      float reset = (mem > 1.0f) ? 1.0f : 0.0f;
      mem = 0.9f * mem + v[i] - reset;
      __stcs(sp + (size_t)(t + i) * Hh, (mem > 1.0f) ? 1.0f : 0.0f);
    }
  }
}

// ---------------------------------------------------------------------------
// K3: gx = [x | spk] @ wih^T + bih  (M=BT, N=768, K=320). BM=128 BN=64 BK=32.
// k-tiles 0,32 read x (stride 64); k-tiles >=64 read spk (stride 256).
// ---------------------------------------------------------------------------
__global__ __launch_bounds__(256) void gx_gemm_kernel(
    const float* __restrict__ x, const float* __restrict__ wih,
    const float* __restrict__ bih) {
  __shared__ float As[32][130];
  __shared__ float Bs[32][66];
  const int row0 = blockIdx.x * 128;
  const int col0 = blockIdx.y * 64;
  const int tid  = threadIdx.x;
  const int tm   = tid & 15;
  const int tn   = tid >> 4;
  float acc[8][4];
#pragma unroll
  for (int i = 0; i < 8; i++)
#pragma unroll
    for (int j = 0; j < 4; j++) acc[i][j] = 0.f;

  const int lm = tid >> 3;
  const int lk = (tid & 7) << 2;

  for (int k0 = 0; k0 < 320; k0 += 32) {
#pragma unroll
    for (int i = 0; i < 4; i++) {
      int m = lm + 32 * i;
      float4 v;
      if (k0 < 64) {
        v = *reinterpret_cast<const float4*>(
            &x[(size_t)(row0 + m) * Cc + k0 + lk]);
      } else {
        v = *reinterpret_cast<const float4*>(
            &g_spk[(size_t)(row0 + m) * Hh + (k0 - 64) + lk]);
      }
      As[lk + 0][m] = v.x; As[lk + 1][m] = v.y;
      As[lk + 2][m] = v.z; As[lk + 3][m] = v.w;
    }
#pragma unroll
    for (int i = 0; i < 2; i++) {
      int n = lm + 32 * i;
      float4 v = *reinterpret_cast<const float4*>(
          &wih[(size_t)(col0 + n) * 320 + k0 + lk]);
      Bs[lk + 0][n] = v.x; Bs[lk + 1][n] = v.y;
      Bs[lk + 2][n] = v.z; Bs[lk + 3][n] = v.w;
    }
    __syncthreads();
#pragma unroll
    for (int kk = 0; kk < 32; kk++) {
      float a[8], b[4];
#pragma unroll
      for (int i = 0; i < 8; i++) a[i] = As[kk][tm + 16 * i];
#pragma unroll
      for (int j = 0; j < 4; j++) b[j] = Bs[kk][tn * 4 + j];
#pragma unroll
      for (int i = 0; i < 8; i++)
#pragma unroll
        for (int j = 0; j < 4; j++) acc[i][j] += a[i] * b[j];
    }
    __syncthreads();
  }
  float4 bv = *reinterpret_cast<const float4*>(&bih[col0 + tn * 4]);
#pragma unroll
  for (int i = 0; i < 8; i++) {
    float4 o;
    o.x = acc[i][0] + bv.x; o.y = acc[i][1] + bv.y;
    o.z = acc[i][2] + bv.z; o.w = acc[i][3] + bv.w;
    *reinterpret_cast<float4*>(
        &g_gx[(size_t)(row0 + tm + 16 * i) * G3 + col0 + tn * 4]) = o;
  }
}

// ---------------------------------------------------------------------------
// K4: GRU scan. 1 cluster(2 CTAs) per batch row; 384 threads/CTA.
// CTA rank r owns gate rows {g*256 + r*128 + d : g in 0..2, d in 0..127}
// and h dims [r*128, r*128+128). whh rows cached fp16 in smem (264-half
// padded rows -> conflict-free). Per step: 384 dots, gate math on 128
// threads, DSMEM h exchange, barrier.cluster. h double-buffered.
// ---------------------------------------------------------------------------
#define GRU_THREADS 384
#define WPAD 264
#define GRU_SMEM (384 * WPAD * 2 + (256 + 256 + 512) * 4)

__device__ __forceinline__ unsigned smem_u32(const void* p) {
  return (unsigned)__cvta_generic_to_shared(p);
}

extern __shared__ char gru_smem_raw[];

__global__ void __cluster_dims__(2, 1, 1) __launch_bounds__(GRU_THREADS, 1)
gru_kernel(const float* __restrict__ whh, const float* __restrict__ bhh) {
  half*  whh_s = reinterpret_cast<half*>(gru_smem_raw);
  float* fbase = reinterpret_cast<float*>(gru_smem_raw + 384 * WPAD * 2);
  float* h_s0 = fbase;          // 256
  float* h_s1 = fbase + 256;    // 256
  float* gh_s = fbase + 512;    // 512: [0:128) pre_r, [128:256) pre_z,
                                //      [256:384) hn,   [384:512) xn
  const int tid = threadIdx.x;
  unsigned rank_u;
  asm("mov.u32 %0, %%cluster_ctarank;" : "=r"(rank_u));
  const int rank = (int)rank_u;
  const int peer = rank ^ 1;
  const int bidx = blockIdx.x >> 1;
  const int g = tid >> 7;        // gate 0..2
  const int d = tid & 127;       // dim within half
  const int jg = g * 256 + rank * 128 + d;   // global gate row

  // cooperative, coalesced whh -> fp16 smem (row `r` holds global row jg(r))
  for (int i4 = tid; i4 < 384 * 64; i4 += GRU_THREADS) {
    int row = i4 >> 6;
    int k4  = (i4 & 63) << 2;
    int grow = (row >> 7) * 256 + rank * 128 + (row & 127);
    float4 v = *reinterpret_cast<const float4*>(&whh[(size_t)grow * 256 + k4]);
    half* ws = whh_s + (size_t)row * WPAD + k4;
    ws[0] = __float2half(v.x); ws[1] = __float2half(v.y);
    ws[2] = __float2half(v.z); ws[3] = __float2half(v.w);
  }
  const float bhh_j = bhh[jg];
  for (int i = tid; i < 256; i += GRU_THREADS) h_s0[i] = 0.f;
  __syncthreads();
  asm volatile("barrier.cluster.arrive.aligned;" ::: "memory");
  asm volatile("barrier.cluster.wait.aligned;" ::: "memory");

  const float* gxp = g_gx + (size_t)bidx * Tt * G3 + jg;
  float gxv = __ldcg(gxp);

  const uint4* wrow =
      reinterpret_cast<const uint4*>(whh_s + (size_t)tid * WPAD);

#pragma unroll 1
  for (int t = 0; t < Tt; t++) {
    float* hr = (t & 1) ? h_s1 : h_s0;
    float* hw = (t & 1) ? h_s0 : h_s1;
    float gxnext = (t + 1 < Tt) ? __ldcg(gxp + (size_t)(t + 1) * G3) : 0.f;

    float a0 = 0.f, a1 = 0.f, a2 = 0.f, a3 = 0.f;
#pragma unroll
    for (int kk = 0; kk < 32; kk++) {
      uint4 w = wrow[kk];
      const float4* hp = reinterpret_cast<const float4*>(hr + kk * 8);
      float4 hA = hp[0];
      float4 hB = hp[1];
      float2 f;
      f = __half22float2(*reinterpret_cast<const half2*>(&w.x));
      a0 += f.x * hA.x; a1 += f.y * hA.y;
      f = __half22float2(*reinterpret_cast<const half2*>(&w.y));
      a2 += f.x * hA.z; a3 += f.y * hA.w;
      f = __half22float2(*reinterpret_cast<const half2*>(&w.z));
      a0 += f.x * hB.x; a1 += f.y * hB.y;
      f = __half22float2(*reinterpret_cast<const half2*>(&w.w));
      a2 += f.x * hB.z; a3 += f.y * hB.w;
    }
    float s = (a0 + a1) + (a2 + a3) + bhh_j;

    if (g == 0)      gh_s[d]       = gxv + s;
    else if (g == 1) gh_s[128 + d] = gxv + s;
    else { gh_s[256 + d] = s; gh_s[384 + d] = gxv; }
    __syncthreads();

    if (tid < 128) {
      float pre_r = gh_s[tid];
      float pre_z = gh_s[128 + tid];
      float hn    = gh_s[256 + tid];
      float xn    = gh_s[384 + tid];
      float r = 1.f / (1.f + __expf(-pre_r));
      float z = 1.f / (1.f + __expf(-pre_z));
      float n = tanhf(xn + r * hn);
      float hold = hr[rank * 128 + tid];
      float hnew = (1.f - z) * n + z * hold;
      hw[rank * 128 + tid] = hnew;
      unsigned laddr = smem_u32(&hw[rank * 128 + tid]);
      unsigned raddr;
      asm volatile("mapa.shared::cluster.u32 %0, %1, %2;"
                   : "=r"(raddr) : "r"(laddr), "r"(peer));
      asm volatile("st.shared::cluster.f32 [%0], %1;"
                   :: "r"(raddr), "f"(hnew) : "memory");
    }
    gxv = gxnext;
    asm volatile("barrier.cluster.arrive.aligned;" ::: "memory");
    asm volatile("barrier.cluster.wait.aligned;" ::: "memory");
  }

  // Tt even -> final full h lives in h_s0 (both CTAs hold a full copy)
  if (rank == 0 && tid < 256) g_hT[bidx * Hh + tid] = h_s0[tid];
}

// ---------------------------------------------------------------------------
// K5: head. out[b,o] = hT[b,:].head_w[o,:] + head_b[o]
// ---------------------------------------------------------------------------
__global__ __launch_bounds__(96) void head_kernel(
    const float* __restrict__ head_w, const float* __restrict__ head_b,
    float* __restrict__ out) {
  const int b = blockIdx.x;
  const int o = threadIdx.x;
  const float* h = g_hT + b * Hh;
  const float* wr = head_w + o * Hh;
  float acc = 0.f;
#pragma unroll 8
  for (int k = 0; k < Hh; k++) acc += h[k] * wr[k];
  out[b * HORd + o] = acc + head_b[o];
}

// ---------------------------------------------------------------------------
extern "C" void kernel_launch(void* const* d_in, const int* in_sizes, int n_in,
                              void* d_out, int out_size) {
  const float* x      = (const float*)d_in[0];
  const float* snn_w  = (const float*)d_in[1];
  const float* snn_b  = (const float*)d_in[2];
  const float* wih    = (const float*)d_in[3];
  const float* whh    = (const float*)d_in[4];
  const float* bih    = (const float*)d_in[5];
  const float* bhh    = (const float*)d_in[6];
  const float* head_w = (const float*)d_in[7];
  const float* head_b = (const float*)d_in[8];
  float* out = (float*)d_out;

  cudaFuncSetAttribute(gru_kernel,
                       cudaFuncAttributeMaxDynamicSharedMemorySize, GRU_SMEM);

  cur_gemm_kernel<<<dim3(BT / 128, Hh / 64), 256>>>(x, snn_w, snn_b);
  lif_kernel<<<Bb, 256>>>();
  gx_gemm_kernel<<<dim3(BT / 128, G3 / 64), 256>>>(x, wih, bih);
  gru_kernel<<<Bb * 2, GRU_THREADS, GRU_SMEM>>>(whh, bhh);
  head_kernel<<<Bb, HORd>>>(head_w, head_b, out);
}

// round 7
// speedup vs baseline: 1.1486x; 1.1486x over previous
#include <cuda_runtime.h>
#include <cuda_fp16.h>
#include <cstdint>

// ---------------------------------------------------------------------------
// HybridForecaster: SNN(LIF) -> GRU -> linear head
// B=64, T=2048, C=64, H=256, HOR=96, BETA=0.9, THR=1.0
// ---------------------------------------------------------------------------

#define Bb   64
#define Tt   2048
#define Cc   64
#define Hh   256
#define G3   768
#define HORd 96
#define BT   (Bb * Tt)

__device__ float g_cur[(size_t)BT * Hh];
__device__ float g_spk[(size_t)BT * Hh];
__device__ float g_gx [(size_t)BT * G3];
__device__ float g_hT [Bb * Hh];

// ------------------------- packed f32x2 helpers ----------------------------
__device__ __forceinline__ unsigned long long ffma2(
    unsigned long long a, unsigned long long b, unsigned long long c) {
  unsigned long long d;
  asm("fma.rn.f32x2 %0, %1, %2, %3;" : "=l"(d) : "l"(a), "l"(b), "l"(c));
  return d;
}
__device__ __forceinline__ unsigned long long splat2(float a) {
  unsigned long long r;
  asm("mov.b64 %0, {%1, %1};" : "=l"(r) : "f"(a));
  return r;
}
__device__ __forceinline__ void unpack2(unsigned long long v, float& lo,
                                        float& hi) {
  asm("mov.b64 {%0, %1}, %2;" : "=f"(lo), "=f"(hi) : "l"(v));
}
__device__ __forceinline__ unsigned bf16pack(float lo, float hi) {
  unsigned r;
  asm("cvt.rn.bf16x2.f32 %0, %1, %2;" : "=r"(r) : "f"(hi), "f"(lo));
  return r;  // low 16 bits <- lo
}
__device__ __forceinline__ float bflo(unsigned r) {
  return __uint_as_float(r << 16);
}
__device__ __forceinline__ float bfhi(unsigned r) {
  return __uint_as_float(r & 0xFFFF0000u);
}
__device__ __forceinline__ unsigned smem_u32(const void* p) {
  return (unsigned)__cvta_generic_to_shared(p);
}

// ---------------------------------------------------------------------------
// K1: cur = x @ snn_w^T + snn_b  (M=BT, N=256, K=64). BM=128 BN=64 BK=32.
// ---------------------------------------------------------------------------
__global__ __launch_bounds__(256) void cur_gemm_kernel(
    const float* __restrict__ x, const float* __restrict__ w,
    const float* __restrict__ bias) {
  __shared__ float As[32][130];
  __shared__ float Bs[32][66];
  const int row0 = blockIdx.x * 128;
  const int col0 = blockIdx.y * 64;
  const int tid  = threadIdx.x;
  const int tm   = tid & 15;
  const int tn   = tid >> 4;
  float acc[8][4];
#pragma unroll
  for (int i = 0; i < 8; i++)
#pragma unroll
    for (int j = 0; j < 4; j++) acc[i][j] = 0.f;

  const int lm = tid >> 3;
  const int lk = (tid & 7) << 2;

  for (int k0 = 0; k0 < 64; k0 += 32) {
#pragma unroll
    for (int i = 0; i < 4; i++) {
      int m = lm + 32 * i;
      float4 v = *reinterpret_cast<const float4*>(
          &x[(size_t)(row0 + m) * Cc + k0 + lk]);
      As[lk + 0][m] = v.x; As[lk + 1][m] = v.y;
      As[lk + 2][m] = v.z; As[lk + 3][m] = v.w;
    }
#pragma unroll
    for (int i = 0; i < 2; i++) {
      int n = lm + 32 * i;
      float4 v = *reinterpret_cast<const float4*>(
          &w[(size_t)(col0 + n) * Cc + k0 + lk]);
      Bs[lk + 0][n] = v.x; Bs[lk + 1][n] = v.y;
      Bs[lk + 2][n] = v.z; Bs[lk + 3][n] = v.w;
    }
    __syncthreads();
#pragma unroll
    for (int kk = 0; kk < 32; kk++) {
      float a[8], b[4];
#pragma unroll
      for (int i = 0; i < 8; i++) a[i] = As[kk][tm + 16 * i];
#pragma unroll
      for (int j = 0; j < 4; j++) b[j] = Bs[kk][tn * 4 + j];
#pragma unroll
      for (int i = 0; i < 8; i++)
#pragma unroll
        for (int j = 0; j < 4; j++) acc[i][j] += a[i] * b[j];
    }
    __syncthreads();
  }
  float4 bv = *reinterpret_cast<const float4*>(&bias[col0 + tn * 4]);
#pragma unroll
  for (int i = 0; i < 8; i++) {
    float4 o;
    o.x = acc[i][0] + bv.x; o.y = acc[i][1] + bv.y;
    o.z = acc[i][2] + bv.z; o.w = acc[i][3] + bv.w;
    *reinterpret_cast<float4*>(
        &g_cur[(size_t)(row0 + tm + 16 * i) * Hh + col0 + tn * 4]) = o;
  }
}

// ---------------------------------------------------------------------------
// K2: LIF scan.
// ---------------------------------------------------------------------------
__global__ __launch_bounds__(256) void lif_kernel() {
  const int b = blockIdx.x;
  const int h = threadIdx.x;
  const float* cp = g_cur + (size_t)b * Tt * Hh + h;
  float* sp = g_spk + (size_t)b * Tt * Hh + h;
  float mem = 0.f;
#pragma unroll 1
  for (int t = 0; t < Tt; t += 16) {
    float v[16];
#pragma unroll
    for (int i = 0; i < 16; i++) v[i] = __ldcs(cp + (size_t)(t + i) * Hh);
#pragma unroll
    for (int i = 0; i < 16; i++) {
      float reset = (mem > 1.0f) ? 1.0f : 0.0f;
      mem = 0.9f * mem + v[i] - reset;
      __stcs(sp + (size_t)(t + i) * Hh, (mem > 1.0f) ? 1.0f : 0.0f);
    }
  }
}

// ---------------------------------------------------------------------------
// K3: gx = [x | spk] @ wih^T + bih  (M=BT, N=768, K=320).
// BM=BN=128, BK=16, 256 threads, 8x8 per thread via packed fma.rn.f32x2.
// ---------------------------------------------------------------------------
#define GPAD 132
__global__ __launch_bounds__(256) void gx_gemm_kernel(
    const float* __restrict__ x, const float* __restrict__ wih,
    const float* __restrict__ bih) {
  __shared__ float As[16][GPAD];
  __shared__ float Bs[16][GPAD];
  const int row0 = blockIdx.x * 128;
  const int col0 = blockIdx.y * 128;
  const int tid  = threadIdx.x;
  const int tm   = tid & 15;
  const int tn   = tid >> 4;

  unsigned long long acc[8][4];
#pragma unroll
  for (int i = 0; i < 8; i++)
#pragma unroll
    for (int j = 0; j < 4; j++) acc[i][j] = 0ull;

  const int lm = tid >> 2;          // 0..63 : row / col within tile-half
  const int lkq = (tid & 3) << 2;   // 0,4,8,12

  float4 ra[2], rb[2];

  auto loadg = [&](int k0) {
#pragma unroll
    for (int i = 0; i < 2; i++) {
      int m = lm + 64 * i;
      if (k0 < 64) {
        ra[i] = *reinterpret_cast<const float4*>(
            &x[(size_t)(row0 + m) * Cc + k0 + lkq]);
      } else {
        ra[i] = *reinterpret_cast<const float4*>(
            &g_spk[(size_t)(row0 + m) * Hh + (k0 - 64) + lkq]);
      }
      rb[i] = *reinterpret_cast<const float4*>(
          &wih[(size_t)(col0 + m) * 320 + k0 + lkq]);
    }
  };

  loadg(0);
#pragma unroll 1
  for (int kt = 0; kt < 20; kt++) {
    __syncthreads();
#pragma unroll
    for (int i = 0; i < 2; i++) {
      int m = lm + 64 * i;
      As[lkq + 0][m] = ra[i].x; As[lkq + 1][m] = ra[i].y;
      As[lkq + 2][m] = ra[i].z; As[lkq + 3][m] = ra[i].w;
      Bs[lkq + 0][m] = rb[i].x; Bs[lkq + 1][m] = rb[i].y;
      Bs[lkq + 2][m] = rb[i].z; Bs[lkq + 3][m] = rb[i].w;
    }
    __syncthreads();
    if (kt < 19) loadg((kt + 1) * 16);

#pragma unroll
    for (int kk = 0; kk < 16; kk++) {
      float4 aA = *reinterpret_cast<const float4*>(&As[kk][tm * 4]);
      float4 aB = *reinterpret_cast<const float4*>(&As[kk][64 + tm * 4]);
      ulonglong2 b0 = *reinterpret_cast<const ulonglong2*>(&Bs[kk][tn * 4]);
      ulonglong2 b1 =
          *reinterpret_cast<const ulonglong2*>(&Bs[kk][64 + tn * 4]);
      unsigned long long bp[4] = {b0.x, b0.y, b1.x, b1.y};
      unsigned long long as8[8] = {splat2(aA.x), splat2(aA.y), splat2(aA.z),
                                   splat2(aA.w), splat2(aB.x), splat2(aB.y),
                                   splat2(aB.z), splat2(aB.w)};
#pragma unroll
      for (int i = 0; i < 8; i++)
#pragma unroll
        for (int j = 0; j < 4; j++) acc[i][j] = ffma2(as8[i], bp[j], acc[i][j]);
    }
  }

  float4 bv0 = *reinterpret_cast<const float4*>(&bih[col0 + tn * 4]);
  float4 bv1 = *reinterpret_cast<const float4*>(&bih[col0 + 64 + tn * 4]);
#pragma unroll
  for (int i = 0; i < 8; i++) {
    int r = row0 + ((i < 4) ? (tm * 4 + i) : (64 + tm * 4 + (i - 4)));
    float4 o0, o1;
    unpack2(acc[i][0], o0.x, o0.y); unpack2(acc[i][1], o0.z, o0.w);
    unpack2(acc[i][2], o1.x, o1.y); unpack2(acc[i][3], o1.z, o1.w);
    o0.x += bv0.x; o0.y += bv0.y; o0.z += bv0.z; o0.w += bv0.w;
    o1.x += bv1.x; o1.y += bv1.y; o1.z += bv1.z; o1.w += bv1.w;
    *reinterpret_cast<float4*>(&g_gx[(size_t)r * G3 + col0 + tn * 4]) = o0;
    *reinterpret_cast<float4*>(&g_gx[(size_t)r * G3 + col0 + 64 + tn * 4]) = o1;
  }
}

// ---------------------------------------------------------------------------
// K4: GRU scan. cluster(2) per batch, 384 threads/CTA, thread owns one gate
// row jg: 112 fp32 weights in registers (f32x2 FMA), 144 bf16 weights in smem
// (full-rate SHL/AND unpack + scalar FFMA). Per-step h exchange via
// st.shared::cluster + mbarrier arrive.release.cluster (no barrier.cluster
// in the loop).
// ---------------------------------------------------------------------------
#define GRU_THREADS 384
#define KREG 112
#define KSM  144
#define NITR (KREG / 8)   // 14
#define NITS (KSM / 8)    // 18
#define WROWB 304         // 144*2=288 -> pad 304 (16-div, 19 chunks: odd)
#define WSM_BYTES (GRU_THREADS * WROWB)     // 116736
#define H0_OFF  WSM_BYTES
#define H1_OFF  (H0_OFF + 1024)
#define GH_OFF  (H1_OFF + 1024)
#define MB_OFF  (GH_OFF + 2048)             // 16B aligned
#define GRU_SMEM (MB_OFF + 16)

extern __shared__ char gru_smem_raw[];

__global__ void __cluster_dims__(2, 1, 1) __launch_bounds__(GRU_THREADS, 1)
gru_kernel(const float* __restrict__ whh, const float* __restrict__ bhh) {
  float* h0 = reinterpret_cast<float*>(gru_smem_raw + H0_OFF);
  float* h1 = reinterpret_cast<float*>(gru_smem_raw + H1_OFF);
  float* gh = reinterpret_cast<float*>(gru_smem_raw + GH_OFF);

  const int tid = threadIdx.x;
  unsigned rank_u;
  asm("mov.u32 %0, %%cluster_ctarank;" : "=r"(rank_u));
  const int rank = (int)rank_u;
  const int peer = rank ^ 1;
  const int bidx = blockIdx.x >> 1;
  const int g = tid >> 7;
  const int d = tid & 127;
  const int jg = g * 256 + rank * 128 + d;

  const float* wr = whh + (size_t)jg * 256;

  // 112 fp32 weights in registers as 56 packed f32x2
  unsigned long long wreg[56];
#pragma unroll
  for (int i = 0; i < 28; i++) {
    ulonglong2 v = *reinterpret_cast<const ulonglong2*>(wr + i * 4);
    wreg[2 * i] = v.x; wreg[2 * i + 1] = v.y;
  }

  // 144 bf16 weights into smem (per-thread row, 16B-aligned, conflict-free)
  unsigned* myw = reinterpret_cast<unsigned*>(gru_smem_raw + tid * WROWB);
#pragma unroll
  for (int i = 0; i < NITS; i++) {
    float4 a = *reinterpret_cast<const float4*>(wr + KREG + i * 8);
    float4 b = *reinterpret_cast<const float4*>(wr + KREG + i * 8 + 4);
    myw[i * 4 + 0] = bf16pack(a.x, a.y);
    myw[i * 4 + 1] = bf16pack(a.z, a.w);
    myw[i * 4 + 2] = bf16pack(b.x, b.y);
    myw[i * 4 + 3] = bf16pack(b.z, b.w);
  }

  const float bhh_j = bhh[jg];
  for (int i = tid; i < 256; i += GRU_THREADS) h0[i] = 0.f;

  const unsigned mb_base = smem_u32(gru_smem_raw + MB_OFF);
  if (tid == 0) {
    asm volatile("mbarrier.init.shared.b64 [%0], %1;" ::"r"(mb_base),
                 "r"(128u) : "memory");
    asm volatile("mbarrier.init.shared.b64 [%0], %1;" ::"r"(mb_base + 8),
                 "r"(128u) : "memory");
  }
  __syncthreads();
  asm volatile("barrier.cluster.arrive.aligned;" ::: "memory");
  asm volatile("barrier.cluster.wait.aligned;" ::: "memory");

  const float* gxp = g_gx + (size_t)bidx * Tt * G3 + jg;
  float gxv = __ldcg(gxp);

  int ph[2] = {0, 0};

#pragma unroll 1
  for (int t = 0; t < Tt; t++) {
    float* hr = (t & 1) ? h1 : h0;
    float* hw = (t & 1) ? h0 : h1;
    const int wb = (t + 1) & 1;  // buffer being written this step
    float gxnext = (t + 1 < Tt) ? __ldcg(gxp + (size_t)(t + 1) * G3) : 0.f;

    // ---- fp32 register region: k in [0,112) via packed f32x2 FMA ----
    unsigned long long acc0 = 0ull, acc1 = 0ull, acc2 = 0ull, acc3 = 0ull;
#pragma unroll
    for (int i = 0; i < NITR; i++) {
      ulonglong2 hA = *reinterpret_cast<const ulonglong2*>(hr + i * 8);
      ulonglong2 hB = *reinterpret_cast<const ulonglong2*>(hr + i * 8 + 4);
      acc0 = ffma2(wreg[4 * i + 0], hA.x, acc0);
      acc1 = ffma2(wreg[4 * i + 1], hA.y, acc1);
      acc2 = ffma2(wreg[4 * i + 2], hB.x, acc2);
      acc3 = ffma2(wreg[4 * i + 3], hB.y, acc3);
    }
    // ---- bf16 smem region: k in [112,256), SHL/AND unpack + FFMA ----
    float a0 = 0.f, a1 = 0.f, a2 = 0.f, a3 = 0.f;
#pragma unroll
    for (int i = 0; i < NITS; i++) {
      uint4 wv = *reinterpret_cast<const uint4*>(myw + i * 4);
      const int k = KREG + i * 8;
      float4 hA = *reinterpret_cast<const float4*>(hr + k);
      float4 hB = *reinterpret_cast<const float4*>(hr + k + 4);
      a0 += bflo(wv.x) * hA.x; a1 += bfhi(wv.x) * hA.y;
      a2 += bflo(wv.y) * hA.z; a3 += bfhi(wv.y) * hA.w;
      a0 += bflo(wv.z) * hB.x; a1 += bfhi(wv.z) * hB.y;
      a2 += bflo(wv.w) * hB.z; a3 += bfhi(wv.w) * hB.w;
    }
    float p0, p1, p2, p3, p4, p5, p6, p7;
    unpack2(acc0, p0, p1); unpack2(acc1, p2, p3);
    unpack2(acc2, p4, p5); unpack2(acc3, p6, p7);
    float s = ((p0 + p1) + (p2 + p3)) + ((p4 + p5) + (p6 + p7)) +
              ((a0 + a1) + (a2 + a3)) + bhh_j;

    if (g == 0)      gh[d]       = gxv + s;
    else if (g == 1) gh[128 + d] = gxv + s;
    else { gh[256 + d] = s; gh[384 + d] = gxv; }
    __syncthreads();

    if (tid < 128) {
      float pre_r = gh[tid];
      float pre_z = gh[128 + tid];
      float hn    = gh[256 + tid];
      float xn    = gh[384 + tid];
      float r = 1.f / (1.f + __expf(-pre_r));
      float z = 1.f / (1.f + __expf(-pre_z));
      float n = tanhf(xn + r * hn);
      float hold = hr[rank * 128 + tid];
      float hnew = (1.f - z) * n + z * hold;
      hw[rank * 128 + tid] = hnew;
      unsigned laddr = smem_u32(&hw[rank * 128 + tid]);
      unsigned raddr, rmb;
      asm volatile("mapa.shared::cluster.u32 %0, %1, %2;"
                   : "=r"(raddr) : "r"(laddr), "r"(peer));
      asm volatile("st.shared::cluster.f32 [%0], %1;"
                   :: "r"(raddr), "f"(hnew) : "memory");
      asm volatile("mapa.shared::cluster.u32 %0, %1, %2;"
                   : "=r"(rmb) : "r"(mb_base + 8u * (unsigned)wb), "r"(peer));
      asm volatile(
          "mbarrier.arrive.release.cluster.shared::cluster.b64 _, [%0];"
          :: "r"(rmb) : "memory");
    }
    gxv = gxnext;
    __syncthreads();
    // wait for peer's 128 h values (acquire at cluster scope)
    {
      unsigned mb = mb_base + 8u * (unsigned)wb;
      unsigned par = (unsigned)ph[wb];
      asm volatile(
          "{\n\t.reg .pred P1;\n\t"
          "GRUW_%=:\n\t"
          "mbarrier.try_wait.parity.acquire.cluster.shared::cta.b64 P1, [%0], "
          "%1;\n\t"
          "@P1 bra GRUD_%=;\n\t"
          "bra GRUW_%=;\n\t"
          "GRUD_%=:\n\t}"
          :: "r"(mb), "r"(par) : "memory");
      ph[wb] ^= 1;
    }
  }

  // last written buffer = (2047+1)&1 = 0 -> h0 complete in both CTAs
  if (rank == 0 && tid < 256) g_hT[bidx * Hh + tid] = h0[tid];
}

// ---------------------------------------------------------------------------
// K5: head.
// ---------------------------------------------------------------------------
__global__ __launch_bounds__(96) void head_kernel(
    const float* __restrict__ head_w, const float* __restrict__ head_b,
    float* __restrict__ out) {
  const int b = blockIdx.x;
  const int o = threadIdx.x;
  const float* h = g_hT + b * Hh;
  const float* wr = head_w + o * Hh;
  float acc = 0.f;
#pragma unroll 8
  for (int k = 0; k < Hh; k++) acc += h[k] * wr[k];
  out[b * HORd + o] = acc + head_b[o];
}

// ---------------------------------------------------------------------------
extern "C" void kernel_launch(void* const* d_in, const int* in_sizes, int n_in,
                              void* d_out, int out_size) {
  const float* x      = (const float*)d_in[0];
  const float* snn_w  = (const float*)d_in[1];
  const float* snn_b  = (const float*)d_in[2];
  const float* wih    = (const float*)d_in[3];
  const float* whh    = (const float*)d_in[4];
  const float* bih    = (const float*)d_in[5];
  const float* bhh    = (const float*)d_in[6];
  const float* head_w = (const float*)d_in[7];
  const float* head_b = (const float*)d_in[8];
  float* out = (float*)d_out;

  cudaFuncSetAttribute(gru_kernel,
                       cudaFuncAttributeMaxDynamicSharedMemorySize, GRU_SMEM);

  cur_gemm_kernel<<<dim3(BT / 128, Hh / 64), 256>>>(x, snn_w, snn_b);
  lif_kernel<<<Bb, 256>>>();
  gx_gemm_kernel<<<dim3(BT / 128, G3 / 128), 256>>>(x, wih, bih);
  gru_kernel<<<Bb * 2, GRU_THREADS, GRU_SMEM>>>(whh, bhh);
  head_kernel<<<Bb, HORd>>>(head_w, head_b, out);
}

// round 9
// speedup vs baseline: 1.1676x; 1.0166x over previous
#include <cuda_runtime.h>
#include <cuda_fp16.h>
#include <cstdint>

// ---------------------------------------------------------------------------
// HybridForecaster: SNN(LIF) -> GRU -> linear head
// B=64, T=2048, C=64, H=256, HOR=96, BETA=0.9, THR=1.0
// ---------------------------------------------------------------------------

#define Bb   64
#define Tt   2048
#define Cc   64
#define Hh   256
#define G3   768
#define HORd 96
#define BT   (Bb * Tt)

__device__ float g_cur[(size_t)BT * Hh];
__device__ float g_spk[(size_t)BT * Hh];
__device__ float g_gx [(size_t)BT * G3];
__device__ float g_hT [Bb * Hh];

// ------------------------- packed f32x2 helpers ----------------------------
__device__ __forceinline__ unsigned long long ffma2(
    unsigned long long a, unsigned long long b, unsigned long long c) {
  unsigned long long d;
  asm("fma.rn.f32x2 %0, %1, %2, %3;" : "=l"(d) : "l"(a), "l"(b), "l"(c));
  return d;
}
__device__ __forceinline__ unsigned long long splat2(float a) {
  unsigned long long r;
  asm("mov.b64 %0, {%1, %1};" : "=l"(r) : "f"(a));
  return r;
}
__device__ __forceinline__ void unpack2(unsigned long long v, float& lo,
                                        float& hi) {
  asm("mov.b64 {%0, %1}, %2;" : "=f"(lo), "=f"(hi) : "l"(v));
}
__device__ __forceinline__ unsigned bf16pack(float lo, float hi) {
  unsigned r;
  asm("cvt.rn.bf16x2.f32 %0, %1, %2;" : "=r"(r) : "f"(hi), "f"(lo));
  return r;  // low 16 bits <- lo
}
__device__ __forceinline__ float bflo(unsigned r) {
  return __uint_as_float(r << 16);
}
__device__ __forceinline__ float bfhi(unsigned r) {
  return __uint_as_float(r & 0xFFFF0000u);
}
__device__ __forceinline__ unsigned smem_u32(const void* p) {
  return (unsigned)__cvta_generic_to_shared(p);
}

// ---------------------------------------------------------------------------
// K1: cur = x @ snn_w^T + snn_b  (M=BT, N=256, K=64). BM=128 BN=64 BK=32.
// ---------------------------------------------------------------------------
__global__ __launch_bounds__(256) void cur_gemm_kernel(
    const float* __restrict__ x, const float* __restrict__ w,
    const float* __restrict__ bias) {
  __shared__ float As[32][130];
  __shared__ float Bs[32][66];
  const int row0 = blockIdx.x * 128;
  const int col0 = blockIdx.y * 64;
  const int tid  = threadIdx.x;
  const int tm   = tid & 15;
  const int tn   = tid >> 4;
  float acc[8][4];
#pragma unroll
  for (int i = 0; i < 8; i++)
#pragma unroll
    for (int j = 0; j < 4; j++) acc[i][j] = 0.f;

  const int lm = tid >> 3;
  const int lk = (tid & 7) << 2;

  for (int k0 = 0; k0 < 64; k0 += 32) {
#pragma unroll
    for (int i = 0; i < 4; i++) {
      int m = lm + 32 * i;
      float4 v = *reinterpret_cast<const float4*>(
          &x[(size_t)(row0 + m) * Cc + k0 + lk]);
      As[lk + 0][m] = v.x; As[lk + 1][m] = v.y;
      As[lk + 2][m] = v.z; As[lk + 3][m] = v.w;
    }
#pragma unroll
    for (int i = 0; i < 2; i++) {
      int n = lm + 32 * i;
      float4 v = *reinterpret_cast<const float4*>(
          &w[(size_t)(col0 + n) * Cc + k0 + lk]);
      Bs[lk + 0][n] = v.x; Bs[lk + 1][n] = v.y;
      Bs[lk + 2][n] = v.z; Bs[lk + 3][n] = v.w;
    }
    __syncthreads();
#pragma unroll
    for (int kk = 0; kk < 32; kk++) {
      float a[8], b[4];
#pragma unroll
      for (int i = 0; i < 8; i++) a[i] = As[kk][tm + 16 * i];
#pragma unroll
      for (int j = 0; j < 4; j++) b[j] = Bs[kk][tn * 4 + j];
#pragma unroll
      for (int i = 0; i < 8; i++)
#pragma unroll
        for (int j = 0; j < 4; j++) acc[i][j] += a[i] * b[j];
    }
    __syncthreads();
  }
  float4 bv = *reinterpret_cast<const float4*>(&bias[col0 + tn * 4]);
#pragma unroll
  for (int i = 0; i < 8; i++) {
    float4 o;
    o.x = acc[i][0] + bv.x; o.y = acc[i][1] + bv.y;
    o.z = acc[i][2] + bv.z; o.w = acc[i][3] + bv.w;
    *reinterpret_cast<float4*>(
        &g_cur[(size_t)(row0 + tm + 16 * i) * Hh + col0 + tn * 4]) = o;
  }
}

// ---------------------------------------------------------------------------
// K2: LIF scan.
// ---------------------------------------------------------------------------
__global__ __launch_bounds__(256) void lif_kernel() {
  const int b = blockIdx.x;
  const int h = threadIdx.x;
  const float* cp = g_cur + (size_t)b * Tt * Hh + h;
  float* sp = g_spk + (size_t)b * Tt * Hh + h;
  float mem = 0.f;
#pragma unroll 1
  for (int t = 0; t < Tt; t += 16) {
    float v[16];
#pragma unroll
    for (int i = 0; i < 16; i++) v[i] = __ldcs(cp + (size_t)(t + i) * Hh);
#pragma unroll
    for (int i = 0; i < 16; i++) {
      float reset = (mem > 1.0f) ? 1.0f : 0.0f;
      mem = 0.9f * mem + v[i] - reset;
      __stcs(sp + (size_t)(t + i) * Hh, (mem > 1.0f) ? 1.0f : 0.0f);
    }
  }
}

// ---------------------------------------------------------------------------
// K3: gx = [x | spk] @ wih^T + bih  (M=BT, N=768, K=320).
// BM=BN=128, BK=16, 256 threads, 8x8 per thread via packed fma.rn.f32x2.
// ---------------------------------------------------------------------------
#define GPAD 132
__global__ __launch_bounds__(256) void gx_gemm_kernel(
    const float* __restrict__ x, const float* __restrict__ wih,
    const float* __restrict__ bih) {
  __shared__ float As[16][GPAD];
  __shared__ float Bs[16][GPAD];
  const int row0 = blockIdx.x * 128;
  const int col0 = blockIdx.y * 128;
  const int tid  = threadIdx.x;
  const int tm   = tid & 15;
  const int tn   = tid >> 4;

  unsigned long long acc[8][4];
#pragma unroll
  for (int i = 0; i < 8; i++)
#pragma unroll
    for (int j = 0; j < 4; j++) acc[i][j] = 0ull;

  const int lm = tid >> 2;
  const int lkq = (tid & 3) << 2;

  float4 ra[2], rb[2];

  auto loadg = [&](int k0) {
#pragma unroll
    for (int i = 0; i < 2; i++) {
      int m = lm + 64 * i;
      if (k0 < 64) {
        ra[i] = *reinterpret_cast<const float4*>(
            &x[(size_t)(row0 + m) * Cc + k0 + lkq]);
      } else {
        ra[i] = *reinterpret_cast<const float4*>(
            &g_spk[(size_t)(row0 + m) * Hh + (k0 - 64) + lkq]);
      }
      rb[i] = *reinterpret_cast<const float4*>(
          &wih[(size_t)(col0 + m) * 320 + k0 + lkq]);
    }
  };

  loadg(0);
#pragma unroll 1
  for (int kt = 0; kt < 20; kt++) {
    __syncthreads();
#pragma unroll
    for (int i = 0; i < 2; i++) {
      int m = lm + 64 * i;
      As[lkq + 0][m] = ra[i].x; As[lkq + 1][m] = ra[i].y;
      As[lkq + 2][m] = ra[i].z; As[lkq + 3][m] = ra[i].w;
      Bs[lkq + 0][m] = rb[i].x; Bs[lkq + 1][m] = rb[i].y;
      Bs[lkq + 2][m] = rb[i].z; Bs[lkq + 3][m] = rb[i].w;
    }
    __syncthreads();
    if (kt < 19) loadg((kt + 1) * 16);

#pragma unroll
    for (int kk = 0; kk < 16; kk++) {
      float4 aA = *reinterpret_cast<const float4*>(&As[kk][tm * 4]);
      float4 aB = *reinterpret_cast<const float4*>(&As[kk][64 + tm * 4]);
      ulonglong2 b0 = *reinterpret_cast<const ulonglong2*>(&Bs[kk][tn * 4]);
      ulonglong2 b1 =
          *reinterpret_cast<const ulonglong2*>(&Bs[kk][64 + tn * 4]);
      unsigned long long bp[4] = {b0.x, b0.y, b1.x, b1.y};
      unsigned long long as8[8] = {splat2(aA.x), splat2(aA.y), splat2(aA.z),
                                   splat2(aA.w), splat2(aB.x), splat2(aB.y),
                                   splat2(aB.z), splat2(aB.w)};
#pragma unroll
      for (int i = 0; i < 8; i++)
#pragma unroll
        for (int j = 0; j < 4; j++) acc[i][j] = ffma2(as8[i], bp[j], acc[i][j]);
    }
  }

  float4 bv0 = *reinterpret_cast<const float4*>(&bih[col0 + tn * 4]);
  float4 bv1 = *reinterpret_cast<const float4*>(&bih[col0 + 64 + tn * 4]);
#pragma unroll
  for (int i = 0; i < 8; i++) {
    int r = row0 + ((i < 4) ? (tm * 4 + i) : (64 + tm * 4 + (i - 4)));
    float4 o0, o1;
    unpack2(acc[i][0], o0.x, o0.y); unpack2(acc[i][1], o0.z, o0.w);
    unpack2(acc[i][2], o1.x, o1.y); unpack2(acc[i][3], o1.z, o1.w);
    o0.x += bv0.x; o0.y += bv0.y; o0.z += bv0.z; o0.w += bv0.w;
    o1.x += bv1.x; o1.y += bv1.y; o1.z += bv1.z; o1.w += bv1.w;
    *reinterpret_cast<float4*>(&g_gx[(size_t)r * G3 + col0 + tn * 4]) = o0;
    *reinterpret_cast<float4*>(&g_gx[(size_t)r * G3 + col0 + 64 + tn * 4]) = o1;
  }
}

// ---------------------------------------------------------------------------
// K4: GRU scan. cluster(2) per batch, 384 threads/CTA, thread owns one gate
// row jg. Weights per k-half (own/peer): 56 fp32 in regs (f32x2 FMA) +
// 72 bf16 in smem. The own-half dot runs BEFORE the mbarrier wait (its h
// values are local from the previous step), hiding the peer-exchange
// latency behind ~650 cycles of compute. mbar[0] is pre-armed so the loop
// is uniform; a drain wait + cluster barrier close the kernel.
// R8 fix: wof/wpf sized 4*NF u64 (28 each), not 2*NF — R7 had OOB UB.
// ---------------------------------------------------------------------------
#define GRU_THREADS 384
#define KF 56                       // fp32-in-reg values per half
#define KB 72                       // bf16-in-smem values per half
#define NF (KF / 8)                 // 7 iters
#define NB (KB / 8)                 // 9 iters
#define WROWB 304                   // 2*KB*2=288B -> pad 304 (16B*19, odd)
#define WSM_BYTES (GRU_THREADS * WROWB)
#define H0_OFF  WSM_BYTES
#define H1_OFF  (H0_OFF + 1024)
#define GH_OFF  (H1_OFF + 1024)
#define MB_OFF  (GH_OFF + 2048)
#define GRU_SMEM (MB_OFF + 16)

extern __shared__ char gru_smem_raw[];

// one half of the dot: KF fp32-reg MACs + KB bf16-smem MACs
#define DOT_HALF(WF, WB, HP)                                                \
  do {                                                                      \
    _Pragma("unroll")                                                       \
    for (int i = 0; i < NF; i++) {                                          \
      ulonglong2 u = *reinterpret_cast<const ulonglong2*>((HP) + i * 8);    \
      ulonglong2 v = *reinterpret_cast<const ulonglong2*>((HP) + i * 8 + 4);\
      A0 = ffma2((WF)[4 * i + 0], u.x, A0);                                 \
      A1 = ffma2((WF)[4 * i + 1], u.y, A1);                                 \
      A2 = ffma2((WF)[4 * i + 2], v.x, A2);                                 \
      A3 = ffma2((WF)[4 * i + 3], v.y, A3);                                 \
    }                                                                       \
    _Pragma("unroll")                                                       \
    for (int i = 0; i < NB; i++) {                                          \
      uint4 wv = *reinterpret_cast<const uint4*>((WB) + i * 4);             \
      float4 hA = *reinterpret_cast<const float4*>((HP) + KF + i * 8);      \
      float4 hB = *reinterpret_cast<const float4*>((HP) + KF + i * 8 + 4);  \
      b0 += bflo(wv.x) * hA.x; b1 += bfhi(wv.x) * hA.y;                     \
      b2 += bflo(wv.y) * hA.z; b3 += bfhi(wv.y) * hA.w;                     \
      b0 += bflo(wv.z) * hB.x; b1 += bfhi(wv.z) * hB.y;                     \
      b2 += bflo(wv.w) * hB.z; b3 += bfhi(wv.w) * hB.w;                     \
    }                                                                       \
  } while (0)

__global__ void __cluster_dims__(2, 1, 1) __launch_bounds__(GRU_THREADS, 1)
gru_kernel(const float* __restrict__ whh, const float* __restrict__ bhh) {
  float* h0 = reinterpret_cast<float*>(gru_smem_raw + H0_OFF);
  float* h1 = reinterpret_cast<float*>(gru_smem_raw + H1_OFF);
  float* gh = reinterpret_cast<float*>(gru_smem_raw + GH_OFF);

  const int tid = threadIdx.x;
  unsigned rank_u;
  asm("mov.u32 %0, %%cluster_ctarank;" : "=r"(rank_u));
  const int rank = (int)rank_u;
  const int peer = rank ^ 1;
  const int bidx = blockIdx.x >> 1;
  const int g = tid >> 7;
  const int d = tid & 127;
  const int jg = g * 256 + rank * 128 + d;
  const int kb_own  = rank * 128;
  const int kb_peer = peer * 128;

  const float* wr = whh + (size_t)jg * 256;

  // fp32 weight regs: own half then peer half (28 u64 each)  [R8 FIX: 4*NF]
  unsigned long long wof[4 * NF], wpf[4 * NF];
#pragma unroll
  for (int i = 0; i < NF; i++) {
    ulonglong2 a = *reinterpret_cast<const ulonglong2*>(wr + kb_own + i * 8);
    ulonglong2 b =
        *reinterpret_cast<const ulonglong2*>(wr + kb_own + i * 8 + 4);
    wof[4 * i + 0] = a.x; wof[4 * i + 1] = a.y;
    wof[4 * i + 2] = b.x; wof[4 * i + 3] = b.y;
  }
#pragma unroll
  for (int i = 0; i < NF; i++) {
    ulonglong2 a = *reinterpret_cast<const ulonglong2*>(wr + kb_peer + i * 8);
    ulonglong2 b =
        *reinterpret_cast<const ulonglong2*>(wr + kb_peer + i * 8 + 4);
    wpf[4 * i + 0] = a.x; wpf[4 * i + 1] = a.y;
    wpf[4 * i + 2] = b.x; wpf[4 * i + 3] = b.y;
  }

  // bf16 smem row: [own 36 u32][peer 36 u32]
  unsigned* myw = reinterpret_cast<unsigned*>(gru_smem_raw + tid * WROWB);
#pragma unroll
  for (int i = 0; i < NB; i++) {
    float4 a = *reinterpret_cast<const float4*>(wr + kb_own + KF + i * 8);
    float4 b = *reinterpret_cast<const float4*>(wr + kb_own + KF + i * 8 + 4);
    myw[4 * i + 0] = bf16pack(a.x, a.y);
    myw[4 * i + 1] = bf16pack(a.z, a.w);
    myw[4 * i + 2] = bf16pack(b.x, b.y);
    myw[4 * i + 3] = bf16pack(b.z, b.w);
  }
#pragma unroll
  for (int i = 0; i < NB; i++) {
    float4 a = *reinterpret_cast<const float4*>(wr + kb_peer + KF + i * 8);
    float4 b = *reinterpret_cast<const float4*>(wr + kb_peer + KF + i * 8 + 4);
    myw[4 * NB + 4 * i + 0] = bf16pack(a.x, a.y);
    myw[4 * NB + 4 * i + 1] = bf16pack(a.z, a.w);
    myw[4 * NB + 4 * i + 2] = bf16pack(b.x, b.y);
    myw[4 * NB + 4 * i + 3] = bf16pack(b.z, b.w);
  }

  const float bhh_j = bhh[jg];
  for (int i = tid; i < 256; i += GRU_THREADS) h0[i] = 0.f;

  const unsigned mb_base = smem_u32(gru_smem_raw + MB_OFF);
  if (tid == 0) {
    asm volatile("mbarrier.init.shared.b64 [%0], %1;" ::"r"(mb_base),
                 "r"(128u) : "memory");
    asm volatile("mbarrier.init.shared.b64 [%0], %1;" ::"r"(mb_base + 8),
                 "r"(128u) : "memory");
  }
  __syncthreads();
  asm volatile("barrier.cluster.arrive.aligned;" ::: "memory");
  asm volatile("barrier.cluster.wait.aligned;" ::: "memory");

  // pre-arm mbar[0] on the peer so iteration 0's wait passes
  if (tid < 128) {
    unsigned rmb;
    asm volatile("mapa.shared::cluster.u32 %0, %1, %2;"
                 : "=r"(rmb) : "r"(mb_base), "r"(peer));
    asm volatile("mbarrier.arrive.release.cluster.shared::cluster.b64 _, [%0];"
                 :: "r"(rmb) : "memory");
  }

  const float* gxp = g_gx + (size_t)bidx * Tt * G3 + jg;
  float gxv = __ldcg(gxp);

  int ph[2] = {0, 0};

#pragma unroll 1
  for (int t = 0; t < Tt; t++) {
    float* hr = (t & 1) ? h1 : h0;
    float* hw = (t & 1) ? h0 : h1;
    const int rb = t & 1;         // barrier for the buffer we READ
    const int wb = (t + 1) & 1;   // barrier for the buffer we WRITE
    float gxnext = (t + 1 < Tt) ? __ldcg(gxp + (size_t)(t + 1) * G3) : 0.f;

    unsigned long long A0 = 0ull, A1 = 0ull, A2 = 0ull, A3 = 0ull;
    float b0 = 0.f, b1 = 0.f, b2 = 0.f, b3 = 0.f;

    // own-half dot: local h, ready since previous __syncthreads
    DOT_HALF(wof, myw, hr + kb_own);

    // wait for peer's half of h(t-1) (acquire at cluster scope)
    {
      unsigned mb = mb_base + 8u * (unsigned)rb;
      unsigned par = (unsigned)ph[rb];
      asm volatile(
          "{\n\t.reg .pred P1;\n\t"
          "GRUW_%=:\n\t"
          "mbarrier.try_wait.parity.acquire.cluster.shared::cta.b64 P1, [%0], "
          "%1;\n\t"
          "@P1 bra GRUD_%=;\n\t"
          "bra GRUW_%=;\n\t"
          "GRUD_%=:\n\t}"
          :: "r"(mb), "r"(par) : "memory");
      ph[rb] ^= 1;
    }

    // peer-half dot
    DOT_HALF(wpf, myw + 4 * NB, hr + kb_peer);

    float p0, p1, p2, p3, p4, p5, p6, p7;
    unpack2(A0, p0, p1); unpack2(A1, p2, p3);
    unpack2(A2, p4, p5); unpack2(A3, p6, p7);
    float s = ((p0 + p1) + (p2 + p3)) + ((p4 + p5) + (p6 + p7)) +
              ((b0 + b1) + (b2 + b3)) + bhh_j;

    if (g == 0)      gh[d]       = gxv + s;
    else if (g == 1) gh[128 + d] = gxv + s;
    else { gh[256 + d] = s; gh[384 + d] = gxv; }
    __syncthreads();

    if (tid < 128) {
      float pre_r = gh[tid];
      float pre_z = gh[128 + tid];
      float hn    = gh[256 + tid];
      float xn    = gh[384 + tid];
      float r = 1.f / (1.f + __expf(-pre_r));
      float z = 1.f / (1.f + __expf(-pre_z));
      float n = tanhf(xn + r * hn);
      float hold = hr[kb_own + tid];
      float hnew = (1.f - z) * n + z * hold;
      hw[kb_own + tid] = hnew;
      unsigned laddr = smem_u32(&hw[kb_own + tid]);
      unsigned raddr, rmb;
      asm volatile("mapa.shared::cluster.u32 %0, %1, %2;"
                   : "=r"(raddr) : "r"(laddr), "r"(peer));
      asm volatile("st.shared::cluster.f32 [%0], %1;"
                   :: "r"(raddr), "f"(hnew) : "memory");
      asm volatile("mapa.shared::cluster.u32 %0, %1, %2;"
                   : "=r"(rmb) : "r"(mb_base + 8u * (unsigned)wb), "r"(peer));
      asm volatile(
          "mbarrier.arrive.release.cluster.shared::cluster.b64 _, [%0];"
          :: "r"(rmb) : "memory");
    }
    gxv = gxnext;
    __syncthreads();  // hw own-half visible for next iteration's own-dot
  }

  // drain the final exchange (t=2047 signaled mbar[0]); then h0 is complete
  {
    unsigned mb = mb_base;
    unsigned par = (unsigned)ph[0];
    asm volatile(
        "{\n\t.reg .pred P1;\n\t"
        "GRUF_%=:\n\t"
        "mbarrier.try_wait.parity.acquire.cluster.shared::cta.b64 P1, [%0], "
        "%1;\n\t"
        "@P1 bra GRUG_%=;\n\t"
        "bra GRUF_%=;\n\t"
        "GRUG_%=:\n\t}"
        :: "r"(mb), "r"(par) : "memory");
  }
  if (rank == 0 && tid < 256) g_hT[bidx * Hh + tid] = h0[tid];

  asm volatile("barrier.cluster.arrive.aligned;" ::: "memory");
  asm volatile("barrier.cluster.wait.aligned;" ::: "memory");
}

// ---------------------------------------------------------------------------
// K5: head.
// ---------------------------------------------------------------------------
__global__ __launch_bounds__(96) void head_kernel(
    const float* __restrict__ head_w, const float* __restrict__ head_b,
    float* __restrict__ out) {
  const int b = blockIdx.x;
  const int o = threadIdx.x;
  const float* h = g_hT + b * Hh;
  const float* wr = head_w + o * Hh;
  float acc = 0.f;
#pragma unroll 8
  for (int k = 0; k < Hh; k++) acc += h[k] * wr[k];
  out[b * HORd + o] = acc + head_b[o];
}

// ---------------------------------------------------------------------------
extern "C" void kernel_launch(void* const* d_in, const int* in_sizes, int n_in,
                              void* d_out, int out_size) {
  const float* x      = (const float*)d_in[0];
  const float* snn_w  = (const float*)d_in[1];
  const float* snn_b  = (const float*)d_in[2];
  const float* wih    = (const float*)d_in[3];
  const float* whh    = (const float*)d_in[4];
  const float* bih    = (const float*)d_in[5];
  const float* bhh    = (const float*)d_in[6];
  const float* head_w = (const float*)d_in[7];
  const float* head_b = (const float*)d_in[8];
  float* out = (float*)d_out;

  cudaFuncSetAttribute(gru_kernel,
                       cudaFuncAttributeMaxDynamicSharedMemorySize, GRU_SMEM);

  cur_gemm_kernel<<<dim3(BT / 128, Hh / 64), 256>>>(x, snn_w, snn_b);
  lif_kernel<<<Bb, 256>>>();
  gx_gemm_kernel<<<dim3(BT / 128, G3 / 128), 256>>>(x, wih, bih);
  gru_kernel<<<Bb * 2, GRU_THREADS, GRU_SMEM>>>(whh, bhh);
  head_kernel<<<Bb, HORd>>>(head_w, head_b, out);
}

// round 10
// speedup vs baseline: 1.1884x; 1.0178x over previous
#include <cuda_runtime.h>
#include <cuda_fp16.h>
#include <cstdint>

// ---------------------------------------------------------------------------
// HybridForecaster: SNN(LIF) -> GRU -> linear head
// B=64, T=2048, C=64, H=256, HOR=96, BETA=0.9, THR=1.0
// ---------------------------------------------------------------------------

#define Bb   64
#define Tt   2048
#define Cc   64
#define Hh   256
#define G3   768
#define HORd 96
#define BT   (Bb * Tt)

__device__ float g_cur[(size_t)BT * Hh];
__device__ float g_spk[(size_t)BT * Hh];
__device__ float g_gx [(size_t)BT * G3];
__device__ float g_hT [Bb * Hh];

// ------------------------- packed f32x2 helpers ----------------------------
__device__ __forceinline__ unsigned long long ffma2(
    unsigned long long a, unsigned long long b, unsigned long long c) {
  unsigned long long d;
  asm("fma.rn.f32x2 %0, %1, %2, %3;" : "=l"(d) : "l"(a), "l"(b), "l"(c));
  return d;
}
__device__ __forceinline__ unsigned long long splat2(float a) {
  unsigned long long r;
  asm("mov.b64 %0, {%1, %1};" : "=l"(r) : "f"(a));
  return r;
}
__device__ __forceinline__ void unpack2(unsigned long long v, float& lo,
                                        float& hi) {
  asm("mov.b64 {%0, %1}, %2;" : "=f"(lo), "=f"(hi) : "l"(v));
}
__device__ __forceinline__ unsigned bf16pack(float lo, float hi) {
  unsigned r;
  asm("cvt.rn.bf16x2.f32 %0, %1, %2;" : "=r"(r) : "f"(hi), "f"(lo));
  return r;  // low 16 bits <- lo
}
__device__ __forceinline__ float bflo(unsigned r) {
  return __uint_as_float(r << 16);
}
__device__ __forceinline__ float bfhi(unsigned r) {
  return __uint_as_float(r & 0xFFFF0000u);
}
__device__ __forceinline__ unsigned smem_u32(const void* p) {
  return (unsigned)__cvta_generic_to_shared(p);
}

// ---------------------------------------------------------------------------
// K1: cur = x @ snn_w^T + snn_b  (M=BT, N=256, K=64). BM=128 BN=64 BK=32.
// ---------------------------------------------------------------------------
__global__ __launch_bounds__(256) void cur_gemm_kernel(
    const float* __restrict__ x, const float* __restrict__ w,
    const float* __restrict__ bias) {
  __shared__ float As[32][130];
  __shared__ float Bs[32][66];
  const int row0 = blockIdx.x * 128;
  const int col0 = blockIdx.y * 64;
  const int tid  = threadIdx.x;
  const int tm   = tid & 15;
  const int tn   = tid >> 4;
  float acc[8][4];
#pragma unroll
  for (int i = 0; i < 8; i++)
#pragma unroll
    for (int j = 0; j < 4; j++) acc[i][j] = 0.f;

  const int lm = tid >> 3;
  const int lk = (tid & 7) << 2;

  for (int k0 = 0; k0 < 64; k0 += 32) {
#pragma unroll
    for (int i = 0; i < 4; i++) {
      int m = lm + 32 * i;
      float4 v = *reinterpret_cast<const float4*>(
          &x[(size_t)(row0 + m) * Cc + k0 + lk]);
      As[lk + 0][m] = v.x; As[lk + 1][m] = v.y;
      As[lk + 2][m] = v.z; As[lk + 3][m] = v.w;
    }
#pragma unroll
    for (int i = 0; i < 2; i++) {
      int n = lm + 32 * i;
      float4 v = *reinterpret_cast<const float4*>(
          &w[(size_t)(col0 + n) * Cc + k0 + lk]);
      Bs[lk + 0][n] = v.x; Bs[lk + 1][n] = v.y;
      Bs[lk + 2][n] = v.z; Bs[lk + 3][n] = v.w;
    }
    __syncthreads();
#pragma unroll
    for (int kk = 0; kk < 32; kk++) {
      float a[8], b[4];
#pragma unroll
      for (int i = 0; i < 8; i++) a[i] = As[kk][tm + 16 * i];
#pragma unroll
      for (int j = 0; j < 4; j++) b[j] = Bs[kk][tn * 4 + j];
#pragma unroll
      for (int i = 0; i < 8; i++)
#pragma unroll
        for (int j = 0; j < 4; j++) acc[i][j] += a[i] * b[j];
    }
    __syncthreads();
  }
  float4 bv = *reinterpret_cast<const float4*>(&bias[col0 + tn * 4]);
#pragma unroll
  for (int i = 0; i < 8; i++) {
    float4 o;
    o.x = acc[i][0] + bv.x; o.y = acc[i][1] + bv.y;
    o.z = acc[i][2] + bv.z; o.w = acc[i][3] + bv.w;
    *reinterpret_cast<float4*>(
        &g_cur[(size_t)(row0 + tm + 16 * i) * Hh + col0 + tn * 4]) = o;
  }
}

// ---------------------------------------------------------------------------
// K2: LIF scan.
// ---------------------------------------------------------------------------
__global__ __launch_bounds__(256) void lif_kernel() {
  const int b = blockIdx.x;
  const int h = threadIdx.x;
  const float* cp = g_cur + (size_t)b * Tt * Hh + h;
  float* sp = g_spk + (size_t)b * Tt * Hh + h;
  float mem = 0.f;
#pragma unroll 1
  for (int t = 0; t < Tt; t += 16) {
    float v[16];
#pragma unroll
    for (int i = 0; i < 16; i++) v[i] = __ldcs(cp + (size_t)(t + i) * Hh);
#pragma unroll
    for (int i = 0; i < 16; i++) {
      float reset = (mem > 1.0f) ? 1.0f : 0.0f;
      mem = 0.9f * mem + v[i] - reset;
      __stcs(sp + (size_t)(t + i) * Hh, (mem > 1.0f) ? 1.0f : 0.0f);
    }
  }
}

// ---------------------------------------------------------------------------
// K3: gx = [x | spk] @ wih^T + bih  (M=BT, N=768, K=320).
// BM=BN=128, BK=16, 256 threads, 8x8 per thread via packed fma.rn.f32x2.
// ---------------------------------------------------------------------------
#define GPAD 132
__global__ __launch_bounds__(256) void gx_gemm_kernel(
    const float* __restrict__ x, const float* __restrict__ wih,
    const float* __restrict__ bih) {
  __shared__ float As[16][GPAD];
  __shared__ float Bs[16][GPAD];
  const int row0 = blockIdx.x * 128;
  const int col0 = blockIdx.y * 128;
  const int tid  = threadIdx.x;
  const int tm   = tid & 15;
  const int tn   = tid >> 4;

  unsigned long long acc[8][4];
#pragma unroll
  for (int i = 0; i < 8; i++)
#pragma unroll
    for (int j = 0; j < 4; j++) acc[i][j] = 0ull;

  const int lm = tid >> 2;
  const int lkq = (tid & 3) << 2;

  float4 ra[2], rb[2];

  auto loadg = [&](int k0) {
#pragma unroll
    for (int i = 0; i < 2; i++) {
      int m = lm + 64 * i;
      if (k0 < 64) {
        ra[i] = *reinterpret_cast<const float4*>(
            &x[(size_t)(row0 + m) * Cc + k0 + lkq]);
      } else {
        ra[i] = *reinterpret_cast<const float4*>(
            &g_spk[(size_t)(row0 + m) * Hh + (k0 - 64) + lkq]);
      }
      rb[i] = *reinterpret_cast<const float4*>(
          &wih[(size_t)(col0 + m) * 320 + k0 + lkq]);
    }
  };

  loadg(0);
#pragma unroll 1
  for (int kt = 0; kt < 20; kt++) {
    __syncthreads();
#pragma unroll
    for (int i = 0; i < 2; i++) {
      int m = lm + 64 * i;
      As[lkq + 0][m] = ra[i].x; As[lkq + 1][m] = ra[i].y;
      As[lkq + 2][m] = ra[i].z; As[lkq + 3][m] = ra[i].w;
      Bs[lkq + 0][m] = rb[i].x; Bs[lkq + 1][m] = rb[i].y;
      Bs[lkq + 2][m] = rb[i].z; Bs[lkq + 3][m] = rb[i].w;
    }
    __syncthreads();
    if (kt < 19) loadg((kt + 1) * 16);

#pragma unroll
    for (int kk = 0; kk < 16; kk++) {
      float4 aA = *reinterpret_cast<const float4*>(&As[kk][tm * 4]);
      float4 aB = *reinterpret_cast<const float4*>(&As[kk][64 + tm * 4]);
      ulonglong2 b0 = *reinterpret_cast<const ulonglong2*>(&Bs[kk][tn * 4]);
      ulonglong2 b1 =
          *reinterpret_cast<const ulonglong2*>(&Bs[kk][64 + tn * 4]);
      unsigned long long bp[4] = {b0.x, b0.y, b1.x, b1.y};
      unsigned long long as8[8] = {splat2(aA.x), splat2(aA.y), splat2(aA.z),
                                   splat2(aA.w), splat2(aB.x), splat2(aB.y),
                                   splat2(aB.z), splat2(aB.w)};
#pragma unroll
      for (int i = 0; i < 8; i++)
#pragma unroll
        for (int j = 0; j < 4; j++) acc[i][j] = ffma2(as8[i], bp[j], acc[i][j]);
    }
  }

  float4 bv0 = *reinterpret_cast<const float4*>(&bih[col0 + tn * 4]);
  float4 bv1 = *reinterpret_cast<const float4*>(&bih[col0 + 64 + tn * 4]);
#pragma unroll
  for (int i = 0; i < 8; i++) {
    int r = row0 + ((i < 4) ? (tm * 4 + i) : (64 + tm * 4 + (i - 4)));
    float4 o0, o1;
    unpack2(acc[i][0], o0.x, o0.y); unpack2(acc[i][1], o0.z, o0.w);
    unpack2(acc[i][2], o1.x, o1.y); unpack2(acc[i][3], o1.z, o1.w);
    o0.x += bv0.x; o0.y += bv0.y; o0.z += bv0.z; o0.w += bv0.w;
    o1.x += bv1.x; o1.y += bv1.y; o1.z += bv1.z; o1.w += bv1.w;
    *reinterpret_cast<float4*>(&g_gx[(size_t)r * G3 + col0 + tn * 4]) = o0;
    *reinterpret_cast<float4*>(&g_gx[(size_t)r * G3 + col0 + 64 + tn * 4]) = o1;
  }
}

// ---------------------------------------------------------------------------
// K4: GRU scan. cluster(2) per batch, 384 threads/CTA; thread owns one of
// the 384 local gate rows (full k=256 dot: 112 fp32 weights in regs via
// f32x2 FMA + 144 bf16 weights in smem).
// NEW protocol (R9): exchange PRE-ACTIVATIONS, not h. Right after its dot,
// each thread applies its sigmoid (g<2) and stores its value into the
// local AND the peer's gh buffer (DSMEM) + arrives on the peer's mbarrier.
// Both CTAs then redundantly compute the full 256-dim gate math locally
// (fast stable tanh), so h is fully local and the peer-wait no longer
// contains the gate chain. gh double-buffered, mbar count=384.
// ---------------------------------------------------------------------------
#define GRU_THREADS 384
#define NFI 14                      // fp32-reg iters (112 weights)
#define NBI 18                      // bf16-smem iters (144 weights)
#define WROWB 304                   // 144*2=288 -> pad 304
#define WSM_BYTES (GRU_THREADS * WROWB)   // 116736
#define H0_OFF  WSM_BYTES
#define H1_OFF  (H0_OFF + 1024)
#define GH_OFF  (H1_OFF + 1024)           // 2 buffers x 1024 floats
#define MB_OFF  (GH_OFF + 8192)
#define GRU_SMEM (MB_OFF + 16)

extern __shared__ char gru_smem_raw[];

__global__ void __cluster_dims__(2, 1, 1) __launch_bounds__(GRU_THREADS, 1)
gru_kernel(const float* __restrict__ whh, const float* __restrict__ bhh) {
  float* h0 = reinterpret_cast<float*>(gru_smem_raw + H0_OFF);
  float* h1 = reinterpret_cast<float*>(gru_smem_raw + H1_OFF);
  float* gh = reinterpret_cast<float*>(gru_smem_raw + GH_OFF);

  const int tid = threadIdx.x;
  unsigned rank_u;
  asm("mov.u32 %0, %%cluster_ctarank;" : "=r"(rank_u));
  const int rank = (int)rank_u;
  const int peer = rank ^ 1;
  const int bidx = blockIdx.x >> 1;
  const int g = tid >> 7;                  // gate 0..2
  const int d = tid & 127;
  const int gdim = rank * 128 + d;         // global h-dim of this row
  const int jg = g * 256 + gdim;           // global gate row

  const float* wr = whh + (size_t)jg * 256;

  // 112 fp32 weights in regs as 56 packed f32x2 (k = 0..111)
  unsigned long long wreg[56];
#pragma unroll
  for (int i = 0; i < 28; i++) {
    ulonglong2 v = *reinterpret_cast<const ulonglong2*>(wr + i * 4);
    wreg[2 * i] = v.x; wreg[2 * i + 1] = v.y;
  }

  // 144 bf16 weights in smem (k = 112..255), per-thread row
  unsigned* myw = reinterpret_cast<unsigned*>(gru_smem_raw + tid * WROWB);
#pragma unroll
  for (int i = 0; i < NBI; i++) {
    float4 a = *reinterpret_cast<const float4*>(wr + 112 + i * 8);
    float4 b = *reinterpret_cast<const float4*>(wr + 112 + i * 8 + 4);
    myw[4 * i + 0] = bf16pack(a.x, a.y);
    myw[4 * i + 1] = bf16pack(a.z, a.w);
    myw[4 * i + 2] = bf16pack(b.x, b.y);
    myw[4 * i + 3] = bf16pack(b.z, b.w);
  }

  const float bhh_j = bhh[jg];
  for (int i = tid; i < 256; i += GRU_THREADS) h0[i] = 0.f;

  const unsigned mb_base = smem_u32(gru_smem_raw + MB_OFF);
  if (tid == 0) {
    asm volatile("mbarrier.init.shared.b64 [%0], %1;" ::"r"(mb_base),
                 "r"(384u) : "memory");
    asm volatile("mbarrier.init.shared.b64 [%0], %1;" ::"r"(mb_base + 8),
                 "r"(384u) : "memory");
  }

  // per-thread gh slot (same offset in both CTAs' gh buffers)
  // layout per buffer: [0:256) r, [256:512) z, [512:1024) interleaved (hn,xn)
  const int off0 = (g == 2) ? (512 + 2 * gdim) : (g * 256 + gdim);
  float* lp0 = gh + off0;
  unsigned rgh0, rmb;
  {
    unsigned lgh = smem_u32(gh) + (unsigned)off0 * 4u;
    asm volatile("mapa.shared::cluster.u32 %0, %1, %2;"
                 : "=r"(rgh0) : "r"(lgh), "r"(peer));
    asm volatile("mapa.shared::cluster.u32 %0, %1, %2;"
                 : "=r"(rmb) : "r"(mb_base), "r"(peer));
  }

  __syncthreads();
  asm volatile("barrier.cluster.arrive.aligned;" ::: "memory");
  asm volatile("barrier.cluster.wait.aligned;" ::: "memory");

  const float* gxp = g_gx + (size_t)bidx * Tt * G3 + jg;
  float gxv = __ldcg(gxp);

  int ph0 = 0, ph1 = 0;

#pragma unroll 1
  for (int t = 0; t < Tt; t++) {
    const float* hr = (t & 1) ? h1 : h0;
    float* hw = (t & 1) ? h0 : h1;
    const int buf = t & 1;
    float gxnext = (t + 1 < Tt) ? __ldcg(gxp + (size_t)(t + 1) * G3) : 0.f;

    // ---- full-row dot over local h(t-1) ----
    unsigned long long A0 = 0ull, A1 = 0ull, A2 = 0ull, A3 = 0ull;
#pragma unroll
    for (int i = 0; i < NFI; i++) {
      ulonglong2 u = *reinterpret_cast<const ulonglong2*>(hr + i * 8);
      ulonglong2 v = *reinterpret_cast<const ulonglong2*>(hr + i * 8 + 4);
      A0 = ffma2(wreg[4 * i + 0], u.x, A0);
      A1 = ffma2(wreg[4 * i + 1], u.y, A1);
      A2 = ffma2(wreg[4 * i + 2], v.x, A2);
      A3 = ffma2(wreg[4 * i + 3], v.y, A3);
    }
    float b0 = 0.f, b1 = 0.f, b2 = 0.f, b3 = 0.f;
#pragma unroll
    for (int i = 0; i < NBI; i++) {
      uint4 wv = *reinterpret_cast<const uint4*>(myw + i * 4);
      float4 hA = *reinterpret_cast<const float4*>(hr + 112 + i * 8);
      float4 hB = *reinterpret_cast<const float4*>(hr + 112 + i * 8 + 4);
      b0 += bflo(wv.x) * hA.x; b1 += bfhi(wv.x) * hA.y;
      b2 += bflo(wv.y) * hA.z; b3 += bfhi(wv.y) * hA.w;
      b0 += bflo(wv.z) * hB.x; b1 += bfhi(wv.z) * hB.y;
      b2 += bflo(wv.w) * hB.z; b3 += bfhi(wv.w) * hB.w;
    }
    float p0, p1, p2, p3, p4, p5, p6, p7;
    unpack2(A0, p0, p1); unpack2(A1, p2, p3);
    unpack2(A2, p4, p5); unpack2(A3, p6, p7);
    float s = ((p0 + p1) + (p2 + p3)) + ((p4 + p5) + (p6 + p7)) +
              ((b0 + b1) + (b2 + b3)) + bhh_j;

    // ---- publish pre-activations (sigmoid applied here for g<2) ----
    const unsigned boff = (unsigned)buf * 4096u;
    if (g == 2) {
      lp0[buf * 1024] = s;
      lp0[buf * 1024 + 1] = gxv;
      asm volatile("st.shared::cluster.f32 [%0], %1;"
                   :: "r"(rgh0 + boff), "f"(s) : "memory");
      asm volatile("st.shared::cluster.f32 [%0], %1;"
                   :: "r"(rgh0 + boff + 4u), "f"(gxv) : "memory");
    } else {
      float v = 1.f / (1.f + __expf(-(gxv + s)));
      lp0[buf * 1024] = v;
      asm volatile("st.shared::cluster.f32 [%0], %1;"
                   :: "r"(rgh0 + boff), "f"(v) : "memory");
    }
    asm volatile("mbarrier.arrive.release.cluster.shared::cluster.b64 _, [%0];"
                 :: "r"(rmb + 8u * (unsigned)buf) : "memory");
    gxv = gxnext;
    __syncthreads();  // local gh writes visible

    // ---- wait for peer's 384 pre-activations ----
    {
      unsigned mb = mb_base + 8u * (unsigned)buf;
      unsigned par = (unsigned)(buf ? ph1 : ph0);
      asm volatile(
          "{\n\t.reg .pred P1;\n\t"
          "GRUW_%=:\n\t"
          "mbarrier.try_wait.parity.acquire.cluster.shared::cta.b64 P1, [%0], "
          "%1;\n\t"
          "@P1 bra GRUD_%=;\n\t"
          "bra GRUW_%=;\n\t"
          "GRUD_%=:\n\t}"
          :: "r"(mb), "r"(par) : "memory");
      if (buf) ph1 ^= 1; else ph0 ^= 1;
    }

    // ---- full gate math, redundantly in both CTAs (256 threads) ----
    if (tid < 256) {
      const float* ghb = gh + buf * 1024;
      float r  = ghb[tid];
      float z  = ghb[256 + tid];
      float hn = ghb[512 + 2 * tid];
      float xn = ghb[512 + 2 * tid + 1];
      float y = xn + r * hn;
      float e = __expf(2.f * y);
      float n = 1.f - __fdividef(2.f, e + 1.f);  // stable tanh(y)
      float hold = hr[tid];
      hw[tid] = (1.f - z) * n + z * hold;
    }
    __syncthreads();  // hw complete before next step's dots
  }

  // t=2047: hw == h0 -> full final h local in both CTAs
  if (rank == 0 && tid < 256) g_hT[bidx * Hh + tid] = h0[tid];

  asm volatile("barrier.cluster.arrive.aligned;" ::: "memory");
  asm volatile("barrier.cluster.wait.aligned;" ::: "memory");
}

// ---------------------------------------------------------------------------
// K5: head.
// ---------------------------------------------------------------------------
__global__ __launch_bounds__(96) void head_kernel(
    const float* __restrict__ head_w, const float* __restrict__ head_b,
    float* __restrict__ out) {
  const int b = blockIdx.x;
  const int o = threadIdx.x;
  const float* h = g_hT + b * Hh;
  const float* wr = head_w + o * Hh;
  float acc = 0.f;
#pragma unroll 8
  for (int k = 0; k < Hh; k++) acc += h[k] * wr[k];
  out[b * HORd + o] = acc + head_b[o];
}

// ---------------------------------------------------------------------------
extern "C" void kernel_launch(void* const* d_in, const int* in_sizes, int n_in,
                              void* d_out, int out_size) {
  const float* x      = (const float*)d_in[0];
  const float* snn_w  = (const float*)d_in[1];
  const float* snn_b  = (const float*)d_in[2];
  const float* wih    = (const float*)d_in[3];
  const float* whh    = (const float*)d_in[4];
  const float* bih    = (const float*)d_in[5];
  const float* bhh    = (const float*)d_in[6];
  const float* head_w = (const float*)d_in[7];
  const float* head_b = (const float*)d_in[8];
  float* out = (float*)d_out;

  cudaFuncSetAttribute(gru_kernel,
                       cudaFuncAttributeMaxDynamicSharedMemorySize, GRU_SMEM);

  cur_gemm_kernel<<<dim3(BT / 128, Hh / 64), 256>>>(x, snn_w, snn_b);
  lif_kernel<<<Bb, 256>>>();
  gx_gemm_kernel<<<dim3(BT / 128, G3 / 128), 256>>>(x, wih, bih);
  gru_kernel<<<Bb * 2, GRU_THREADS, GRU_SMEM>>>(whh, bhh);
  head_kernel<<<Bb, HORd>>>(head_w, head_b, out);
}

// round 12
// speedup vs baseline: 1.3532x; 1.1386x over previous
#include <cuda_runtime.h>
#include <cuda_bf16.h>
#include <cstdint>

// ---------------------------------------------------------------------------
// HybridForecaster: SNN(LIF) -> GRU -> linear head
// B=64, T=2048, C=64, H=256, HOR=96, BETA=0.9, THR=1.0
// R11: gx via SPLIT-PRECISION bf16 mma.sync:
//      gx = A_hi.W_hi^T + A_hi.W_lo^T + A_lo.W_hi^T   (A_lo only x-cols)
// ---------------------------------------------------------------------------

#define Bb   64
#define Tt   2048
#define Cc   64
#define Hh   256
#define G3   768
#define KA   320
#define HORd 96
#define BT   (Bb * Tt)

__device__ float g_cur[(size_t)BT * Hh];                 // 134 MB
__device__ __nv_bfloat16 g_a [(size_t)BT * KA];          // 84 MB  [x|spk] hi
__device__ __nv_bfloat16 g_al[(size_t)BT * Cc];          // 17 MB  x lo
__device__ __nv_bfloat16 g_wh[(size_t)G3 * KA];          // wih hi
__device__ __nv_bfloat16 g_wl[(size_t)G3 * KA];          // wih lo
__device__ float g_gx [(size_t)BT * G3];                 // 402 MB
__device__ float g_hT [Bb * Hh];

// ------------------------- packed helpers ----------------------------------
__device__ __forceinline__ unsigned long long ffma2(
    unsigned long long a, unsigned long long b, unsigned long long c) {
  unsigned long long d;
  asm("fma.rn.f32x2 %0, %1, %2, %3;" : "=l"(d) : "l"(a), "l"(b), "l"(c));
  return d;
}
__device__ __forceinline__ void unpack2(unsigned long long v, float& lo,
                                        float& hi) {
  asm("mov.b64 {%0, %1}, %2;" : "=f"(lo), "=f"(hi) : "l"(v));
}
__device__ __forceinline__ unsigned bf16pack(float lo, float hi) {
  unsigned r;
  asm("cvt.rn.bf16x2.f32 %0, %1, %2;" : "=r"(r) : "f"(hi), "f"(lo));
  return r;  // low 16 bits <- lo
}
__device__ __forceinline__ float bflo(unsigned r) {
  return __uint_as_float(r << 16);
}
__device__ __forceinline__ float bfhi(unsigned r) {
  return __uint_as_float(r & 0xFFFF0000u);
}
__device__ __forceinline__ unsigned smem_u32(const void* p) {
  return (unsigned)__cvta_generic_to_shared(p);
}
// split one float into bf16 hi + bf16 lo
__device__ __forceinline__ void bfsplit(float x, __nv_bfloat16& hi,
                                        __nv_bfloat16& lo) {
  hi = __float2bfloat16(x);
  lo = __float2bfloat16(x - __bfloat162float(hi));
}

// ---------------------------------------------------------------------------
// K1: cur = x @ snn_w^T + snn_b  (fp32 — feeds threshold logic)
// ---------------------------------------------------------------------------
__global__ __launch_bounds__(256) void cur_gemm_kernel(
    const float* __restrict__ x, const float* __restrict__ w,
    const float* __restrict__ bias) {
  __shared__ float As[32][130];
  __shared__ float Bs[32][66];
  const int row0 = blockIdx.x * 128;
  const int col0 = blockIdx.y * 64;
  const int tid  = threadIdx.x;
  const int tm   = tid & 15;
  const int tn   = tid >> 4;
  float acc[8][4];
#pragma unroll
  for (int i = 0; i < 8; i++)
#pragma unroll
    for (int j = 0; j < 4; j++) acc[i][j] = 0.f;

  const int lm = tid >> 3;
  const int lk = (tid & 7) << 2;

  for (int k0 = 0; k0 < 64; k0 += 32) {
#pragma unroll
    for (int i = 0; i < 4; i++) {
      int m = lm + 32 * i;
      float4 v = *reinterpret_cast<const float4*>(
          &x[(size_t)(row0 + m) * Cc + k0 + lk]);
      As[lk + 0][m] = v.x; As[lk + 1][m] = v.y;
      As[lk + 2][m] = v.z; As[lk + 3][m] = v.w;
    }
#pragma unroll
    for (int i = 0; i < 2; i++) {
      int n = lm + 32 * i;
      float4 v = *reinterpret_cast<const float4*>(
          &w[(size_t)(col0 + n) * Cc + k0 + lk]);
      Bs[lk + 0][n] = v.x; Bs[lk + 1][n] = v.y;
      Bs[lk + 2][n] = v.z; Bs[lk + 3][n] = v.w;
    }
    __syncthreads();
#pragma unroll
    for (int kk = 0; kk < 32; kk++) {
      float a[8], b[4];
#pragma unroll
      for (int i = 0; i < 8; i++) a[i] = As[kk][tm + 16 * i];
#pragma unroll
      for (int j = 0; j < 4; j++) b[j] = Bs[kk][tn * 4 + j];
#pragma unroll
      for (int i = 0; i < 8; i++)
#pragma unroll
        for (int j = 0; j < 4; j++) acc[i][j] += a[i] * b[j];
    }
    __syncthreads();
  }
  float4 bv = *reinterpret_cast<const float4*>(&bias[col0 + tn * 4]);
#pragma unroll
  for (int i = 0; i < 8; i++) {
    float4 o;
    o.x = acc[i][0] + bv.x; o.y = acc[i][1] + bv.y;
    o.z = acc[i][2] + bv.z; o.w = acc[i][3] + bv.w;
    *reinterpret_cast<float4*>(
        &g_cur[(size_t)(row0 + tm + 16 * i) * Hh + col0 + tn * 4]) = o;
  }
}

// ---------------------------------------------------------------------------
// K2a: x -> bf16 hi into g_a[:,0:64], lo into g_al
// ---------------------------------------------------------------------------
__global__ __launch_bounds__(256) void xcvt_kernel(const float* __restrict__ x) {
  int idx8 = blockIdx.x * 256 + threadIdx.x;     // one per 8 elements
  int row = idx8 >> 3;
  int c8  = (idx8 & 7) << 3;
  float v[8];
  *reinterpret_cast<float4*>(v) =
      *reinterpret_cast<const float4*>(&x[(size_t)row * Cc + c8]);
  *reinterpret_cast<float4*>(v + 4) =
      *reinterpret_cast<const float4*>(&x[(size_t)row * Cc + c8 + 4]);
  __nv_bfloat16 hi[8], lo[8];
#pragma unroll
  for (int i = 0; i < 8; i++) bfsplit(v[i], hi[i], lo[i]);
  *reinterpret_cast<uint4*>(&g_a [(size_t)row * KA + c8]) =
      *reinterpret_cast<uint4*>(hi);
  *reinterpret_cast<uint4*>(&g_al[(size_t)row * Cc + c8]) =
      *reinterpret_cast<uint4*>(lo);
}

// K2b: wih -> bf16 hi/lo
__global__ __launch_bounds__(256) void wcvt_kernel(
    const float* __restrict__ wih) {
  int idx8 = blockIdx.x * 256 + threadIdx.x;
  int base = idx8 << 3;
  float v[8];
  *reinterpret_cast<float4*>(v) =
      *reinterpret_cast<const float4*>(&wih[base]);
  *reinterpret_cast<float4*>(v + 4) =
      *reinterpret_cast<const float4*>(&wih[base + 4]);
  __nv_bfloat16 hi[8], lo[8];
#pragma unroll
  for (int i = 0; i < 8; i++) bfsplit(v[i], hi[i], lo[i]);
  *reinterpret_cast<uint4*>(&g_wh[base]) = *reinterpret_cast<uint4*>(hi);
  *reinterpret_cast<uint4*>(&g_wl[base]) = *reinterpret_cast<uint4*>(lo);
}

// ---------------------------------------------------------------------------
// K3: LIF scan -> bf16 spikes (exact in bf16) into g_a[:,64:320]
// ---------------------------------------------------------------------------
__global__ __launch_bounds__(256) void lif_kernel() {
  const int b = blockIdx.x;
  const int h = threadIdx.x;
  const float* cp = g_cur + (size_t)b * Tt * Hh + h;
  __nv_bfloat16* sp = g_a + (size_t)b * Tt * KA + 64 + h;
  const __nv_bfloat16 one = __float2bfloat16(1.0f);
  const __nv_bfloat16 zero = __float2bfloat16(0.0f);
  float mem = 0.f;
#pragma unroll 1
  for (int t = 0; t < Tt; t += 16) {
    float v[16];
#pragma unroll
    for (int i = 0; i < 16; i++) v[i] = __ldcs(cp + (size_t)(t + i) * Hh);
#pragma unroll
    for (int i = 0; i < 16; i++) {
      float reset = (mem > 1.0f) ? 1.0f : 0.0f;
      mem = 0.9f * mem + v[i] - reset;
      sp[(size_t)(t + i) * KA] = (mem > 1.0f) ? one : zero;
    }
  }
}

// ---------------------------------------------------------------------------
// K4: gx split-precision MMA (M=BT, N=768, K=320)
// BM=128 BN=64 BK=32, 8 warps (4m x 2n), warp tile 32x32.
// acc += A_hi.B_hi + A_hi.B_lo  (all kt) ;  acc += A_lo.B_hi (kt<2, k<64)
// ---------------------------------------------------------------------------
#define APAD 40
__global__ __launch_bounds__(256) void gx_mma_kernel(
    const float* __restrict__ bih) {
  __shared__ __nv_bfloat16 As [128][APAD];
  __shared__ __nv_bfloat16 Asl[128][APAD];
  __shared__ __nv_bfloat16 Bh [64][APAD];
  __shared__ __nv_bfloat16 Bl [64][APAD];
  const int col0 = blockIdx.x * 64;   // n fastest -> A band L2 reuse
  const int row0 = blockIdx.y * 128;
  const int tid  = threadIdx.x;
  const int warp = tid >> 5;
  const int lane = tid & 31;
  const int wm = warp & 3;
  const int wn = warp >> 2;

  float acc[2][4][4];
#pragma unroll
  for (int mi = 0; mi < 2; mi++)
#pragma unroll
    for (int ni = 0; ni < 4; ni++)
#pragma unroll
      for (int r = 0; r < 4; r++) acc[mi][ni][r] = 0.f;

  const int lmat = lane >> 3, lr = lane & 7;
  const int a_row_base = wm * 32 + lr + (lmat & 1) * 8;
  const int a_col_off  = (lmat >> 1) * 8;
  const int b_row_base = wn * 32 + (lmat >> 1) * 8 + lr;
  const int b_col_off  = (lmat & 1) * 8;

  uint4 rga[2], rgal[2], rgbh, rgbl;
  const int gr = tid >> 2, gqc = tid & 3;       // B tiles: 64 rows x 4 quads
  auto loadg = [&](int kt) {
    int k0 = kt * 32;
#pragma unroll
    for (int i = 0; i < 2; i++) {
      int q = tid + i * 256;
      int r = q >> 2, qc = q & 3;
      rga[i] = *reinterpret_cast<const uint4*>(
          &g_a[(size_t)(row0 + r) * KA + k0 + qc * 8]);
      if (kt < 2)
        rgal[i] = *reinterpret_cast<const uint4*>(
            &g_al[(size_t)(row0 + r) * Cc + k0 + qc * 8]);
    }
    rgbh = *reinterpret_cast<const uint4*>(
        &g_wh[(size_t)(col0 + gr) * KA + k0 + gqc * 8]);
    rgbl = *reinterpret_cast<const uint4*>(
        &g_wl[(size_t)(col0 + gr) * KA + k0 + gqc * 8]);
  };

  loadg(0);
#pragma unroll 1
  for (int kt = 0; kt < 10; kt++) {
    __syncthreads();
#pragma unroll
    for (int i = 0; i < 2; i++) {
      int q = tid + i * 256;
      int r = q >> 2, qc = q & 3;
      *reinterpret_cast<uint4*>(&As[r][qc * 8]) = rga[i];
      if (kt < 2) *reinterpret_cast<uint4*>(&Asl[r][qc * 8]) = rgal[i];
    }
    *reinterpret_cast<uint4*>(&Bh[gr][gqc * 8]) = rgbh;
    *reinterpret_cast<uint4*>(&Bl[gr][gqc * 8]) = rgbl;
    __syncthreads();
    if (kt < 9) loadg(kt + 1);

#pragma unroll
    for (int k0 = 0; k0 < 32; k0 += 16) {
      unsigned a[2][4], bh[2][4], bl[2][4];
#pragma unroll
      for (int mi = 0; mi < 2; mi++) {
        unsigned addr = smem_u32(&As[a_row_base + mi * 16][k0 + a_col_off]);
        asm volatile(
            "ldmatrix.sync.aligned.m8n8.x4.shared.b16 {%0,%1,%2,%3}, [%4];"
            : "=r"(a[mi][0]), "=r"(a[mi][1]), "=r"(a[mi][2]), "=r"(a[mi][3])
            : "r"(addr));
      }
#pragma unroll
      for (int np = 0; np < 2; np++) {
        unsigned addr = smem_u32(&Bh[b_row_base + np * 16][k0 + b_col_off]);
        asm volatile(
            "ldmatrix.sync.aligned.m8n8.x4.shared.b16 {%0,%1,%2,%3}, [%4];"
            : "=r"(bh[np][0]), "=r"(bh[np][1]), "=r"(bh[np][2]),
              "=r"(bh[np][3])
            : "r"(addr));
        unsigned addr2 = smem_u32(&Bl[b_row_base + np * 16][k0 + b_col_off]);
        asm volatile(
            "ldmatrix.sync.aligned.m8n8.x4.shared.b16 {%0,%1,%2,%3}, [%4];"
            : "=r"(bl[np][0]), "=r"(bl[np][1]), "=r"(bl[np][2]),
              "=r"(bl[np][3])
            : "r"(addr2));
      }
#pragma unroll
      for (int mi = 0; mi < 2; mi++)
#pragma unroll
        for (int ni = 0; ni < 4; ni++) {
          unsigned h0 = bh[ni >> 1][(ni & 1) * 2 + 0];
          unsigned h1 = bh[ni >> 1][(ni & 1) * 2 + 1];
          asm volatile(
              "mma.sync.aligned.m16n8k16.row.col.f32.bf16.bf16.f32 "
              "{%0,%1,%2,%3}, {%4,%5,%6,%7}, {%8,%9}, {%0,%1,%2,%3};"
              : "+f"(acc[mi][ni][0]), "+f"(acc[mi][ni][1]),
                "+f"(acc[mi][ni][2]), "+f"(acc[mi][ni][3])
              : "r"(a[mi][0]), "r"(a[mi][1]), "r"(a[mi][2]), "r"(a[mi][3]),
                "r"(h0), "r"(h1));
          unsigned l0 = bl[ni >> 1][(ni & 1) * 2 + 0];
          unsigned l1 = bl[ni >> 1][(ni & 1) * 2 + 1];
          asm volatile(
              "mma.sync.aligned.m16n8k16.row.col.f32.bf16.bf16.f32 "
              "{%0,%1,%2,%3}, {%4,%5,%6,%7}, {%8,%9}, {%0,%1,%2,%3};"
              : "+f"(acc[mi][ni][0]), "+f"(acc[mi][ni][1]),
                "+f"(acc[mi][ni][2]), "+f"(acc[mi][ni][3])
              : "r"(a[mi][0]), "r"(a[mi][1]), "r"(a[mi][2]), "r"(a[mi][3]),
                "r"(l0), "r"(l1));
        }
      if (kt < 2) {
        unsigned al[2][4];
#pragma unroll
        for (int mi = 0; mi < 2; mi++) {
          unsigned addr =
              smem_u32(&Asl[a_row_base + mi * 16][k0 + a_col_off]);
          asm volatile(
              "ldmatrix.sync.aligned.m8n8.x4.shared.b16 {%0,%1,%2,%3}, [%4];"
              : "=r"(al[mi][0]), "=r"(al[mi][1]), "=r"(al[mi][2]),
                "=r"(al[mi][3])
              : "r"(addr));
        }
#pragma unroll
        for (int mi = 0; mi < 2; mi++)
#pragma unroll
          for (int ni = 0; ni < 4; ni++) {
            unsigned h0 = bh[ni >> 1][(ni & 1) * 2 + 0];
            unsigned h1 = bh[ni >> 1][(ni & 1) * 2 + 1];
            asm volatile(
                "mma.sync.aligned.m16n8k16.row.col.f32.bf16.bf16.f32 "
                "{%0,%1,%2,%3}, {%4,%5,%6,%7}, {%8,%9}, {%0,%1,%2,%3};"
                : "+f"(acc[mi][ni][0]), "+f"(acc[mi][ni][1]),
                  "+f"(acc[mi][ni][2]), "+f"(acc[mi][ni][3])
                : "r"(al[mi][0]), "r"(al[mi][1]), "r"(al[mi][2]),
                  "r"(al[mi][3]), "r"(h0), "r"(h1));
          }
      }
    }
  }

  const int gp = lane >> 2, tg = lane & 3;
#pragma unroll
  for (int mi = 0; mi < 2; mi++) {
#pragma unroll
    for (int ni = 0; ni < 4; ni++) {
      int col = col0 + wn * 32 + ni * 8 + tg * 2;
      float bx = bih[col], by = bih[col + 1];
      int r0 = row0 + wm * 32 + mi * 16 + gp;
      float2 o0 = {acc[mi][ni][0] + bx, acc[mi][ni][1] + by};
      float2 o1 = {acc[mi][ni][2] + bx, acc[mi][ni][3] + by};
      *reinterpret_cast<float2*>(&g_gx[(size_t)r0 * G3 + col]) = o0;
      *reinterpret_cast<float2*>(&g_gx[(size_t)(r0 + 8) * G3 + col]) = o1;
    }
  }
}

// ---------------------------------------------------------------------------
// K5: GRU scan (unchanged from R9/R10). cluster(2)/batch, pre-activation
// exchange via DSMEM + mbarrier; redundant gate math in both CTAs.
// ---------------------------------------------------------------------------
#define GRU_THREADS 384
#define NFI 14
#define NBI 18
#define WROWB 304
#define WSM_BYTES (GRU_THREADS * WROWB)
#define H0_OFF  WSM_BYTES
#define H1_OFF  (H0_OFF + 1024)
#define GH_OFF  (H1_OFF + 1024)
#define MB_OFF  (GH_OFF + 8192)
#define GRU_SMEM (MB_OFF + 16)

extern __shared__ char gru_smem_raw[];

__global__ void __cluster_dims__(2, 1, 1) __launch_bounds__(GRU_THREADS, 1)
gru_kernel(const float* __restrict__ whh, const float* __restrict__ bhh) {
  float* h0 = reinterpret_cast<float*>(gru_smem_raw + H0_OFF);
  float* h1 = reinterpret_cast<float*>(gru_smem_raw + H1_OFF);
  float* gh = reinterpret_cast<float*>(gru_smem_raw + GH_OFF);

  const int tid = threadIdx.x;
  unsigned rank_u;
  asm("mov.u32 %0, %%cluster_ctarank;" : "=r"(rank_u));
  const int rank = (int)rank_u;
  const int peer = rank ^ 1;
  const int bidx = blockIdx.x >> 1;
  const int g = tid >> 7;
  const int d = tid & 127;
  const int gdim = rank * 128 + d;
  const int jg = g * 256 + gdim;

  const float* wr = whh + (size_t)jg * 256;

  unsigned long long wreg[56];
#pragma unroll
  for (int i = 0; i < 28; i++) {
    ulonglong2 v = *reinterpret_cast<const ulonglong2*>(wr + i * 4);
    wreg[2 * i] = v.x; wreg[2 * i + 1] = v.y;
  }

  unsigned* myw = reinterpret_cast<unsigned*>(gru_smem_raw + tid * WROWB);
#pragma unroll
  for (int i = 0; i < NBI; i++) {
    float4 a = *reinterpret_cast<const float4*>(wr + 112 + i * 8);
    float4 b = *reinterpret_cast<const float4*>(wr + 112 + i * 8 + 4);
    myw[4 * i + 0] = bf16pack(a.x, a.y);
    myw[4 * i + 1] = bf16pack(a.z, a.w);
    myw[4 * i + 2] = bf16pack(b.x, b.y);
    myw[4 * i + 3] = bf16pack(b.z, b.w);
  }

  const float bhh_j = bhh[jg];
  for (int i = tid; i < 256; i += GRU_THREADS) h0[i] = 0.f;

  const unsigned mb_base = smem_u32(gru_smem_raw + MB_OFF);
  if (tid == 0) {
    asm volatile("mbarrier.init.shared.b64 [%0], %1;" ::"r"(mb_base),
                 "r"(384u) : "memory");
    asm volatile("mbarrier.init.shared.b64 [%0], %1;" ::"r"(mb_base + 8),
                 "r"(384u) : "memory");
  }

  const int off0 = (g == 2) ? (512 + 2 * gdim) : (g * 256 + gdim);
  float* lp0 = gh + off0;
  unsigned rgh0, rmb;
  {
    unsigned lgh = smem_u32(gh) + (unsigned)off0 * 4u;
    asm volatile("mapa.shared::cluster.u32 %0, %1, %2;"
                 : "=r"(rgh0) : "r"(lgh), "r"(peer));
    asm volatile("mapa.shared::cluster.u32 %0, %1, %2;"
                 : "=r"(rmb) : "r"(mb_base), "r"(peer));
  }

  __syncthreads();
  asm volatile("barrier.cluster.arrive.aligned;" ::: "memory");
  asm volatile("barrier.cluster.wait.aligned;" ::: "memory");

  const float* gxp = g_gx + (size_t)bidx * Tt * G3 + jg;
  float gxv = __ldcg(gxp);

  int ph0 = 0, ph1 = 0;

#pragma unroll 1
  for (int t = 0; t < Tt; t++) {
    const float* hr = (t & 1) ? h1 : h0;
    float* hw = (t & 1) ? h0 : h1;
    const int buf = t & 1;
    float gxnext = (t + 1 < Tt) ? __ldcg(gxp + (size_t)(t + 1) * G3) : 0.f;

    unsigned long long A0 = 0ull, A1 = 0ull, A2 = 0ull, A3 = 0ull;
#pragma unroll
    for (int i = 0; i < NFI; i++) {
      ulonglong2 u = *reinterpret_cast<const ulonglong2*>(hr + i * 8);
      ulonglong2 v = *reinterpret_cast<const ulonglong2*>(hr + i * 8 + 4);
      A0 = ffma2(wreg[4 * i + 0], u.x, A0);
      A1 = ffma2(wreg[4 * i + 1], u.y, A1);
      A2 = ffma2(wreg[4 * i + 2], v.x, A2);
      A3 = ffma2(wreg[4 * i + 3], v.y, A3);
    }
    float b0 = 0.f, b1 = 0.f, b2 = 0.f, b3 = 0.f;
#pragma unroll
    for (int i = 0; i < NBI; i++) {
      uint4 wv = *reinterpret_cast<const uint4*>(myw + i * 4);
      float4 hA = *reinterpret_cast<const float4*>(hr + 112 + i * 8);
      float4 hB = *reinterpret_cast<const float4*>(hr + 112 + i * 8 + 4);
      b0 += bflo(wv.x) * hA.x; b1 += bfhi(wv.x) * hA.y;
      b2 += bflo(wv.y) * hA.z; b3 += bfhi(wv.y) * hA.w;
      b0 += bflo(wv.z) * hB.x; b1 += bfhi(wv.z) * hB.y;
      b2 += bflo(wv.w) * hB.z; b3 += bfhi(wv.w) * hB.w;
    }
    float p0, p1, p2, p3, p4, p5, p6, p7;
    unpack2(A0, p0, p1); unpack2(A1, p2, p3);
    unpack2(A2, p4, p5); unpack2(A3, p6, p7);
    float s = ((p0 + p1) + (p2 + p3)) + ((p4 + p5) + (p6 + p7)) +
              ((b0 + b1) + (b2 + b3)) + bhh_j;

    const unsigned boff = (unsigned)buf * 4096u;
    if (g == 2) {
      lp0[buf * 1024] = s;
      lp0[buf * 1024 + 1] = gxv;
      asm volatile("st.shared::cluster.f32 [%0], %1;"
                   :: "r"(rgh0 + boff), "f"(s) : "memory");
      asm volatile("st.shared::cluster.f32 [%0], %1;"
                   :: "r"(rgh0 + boff + 4u), "f"(gxv) : "memory");
    } else {
      float v = 1.f / (1.f + __expf(-(gxv + s)));
      lp0[buf * 1024] = v;
      asm volatile("st.shared::cluster.f32 [%0], %1;"
                   :: "r"(rgh0 + boff), "f"(v) : "memory");
    }
    asm volatile("mbarrier.arrive.release.cluster.shared::cluster.b64 _, [%0];"
                 :: "r"(rmb + 8u * (unsigned)buf) : "memory");
    gxv = gxnext;
    __syncthreads();

    {
      unsigned mb = mb_base + 8u * (unsigned)buf;
      unsigned par = (unsigned)(buf ? ph1 : ph0);
      asm volatile(
          "{\n\t.reg .pred P1;\n\t"
          "GRUW_%=:\n\t"
          "mbarrier.try_wait.parity.acquire.cluster.shared::cta.b64 P1, [%0], "
          "%1;\n\t"
          "@P1 bra GRUD_%=;\n\t"
          "bra GRUW_%=;\n\t"
          "GRUD_%=:\n\t}"
          :: "r"(mb), "r"(par) : "memory");
      if (buf) ph1 ^= 1; else ph0 ^= 1;
    }

    if (tid < 256) {
      const float* ghb = gh + buf * 1024;
      float r  = ghb[tid];
      float z  = ghb[256 + tid];
      float hn = ghb[512 + 2 * tid];
      float xn = ghb[512 + 2 * tid + 1];
      float y = xn + r * hn;
      float e = __expf(2.f * y);
      float n = 1.f - __fdividef(2.f, e + 1.f);
      float hold = hr[tid];
      hw[tid] = (1.f - z) * n + z * hold;
    }
    __syncthreads();
  }

  if (rank == 0 && tid < 256) g_hT[bidx * Hh + tid] = h0[tid];

  asm volatile("barrier.cluster.arrive.aligned;" ::: "memory");
  asm volatile("barrier.cluster.wait.aligned;" ::: "memory");
}

// ---------------------------------------------------------------------------
// K6: head.
// ---------------------------------------------------------------------------
__global__ __launch_bounds__(96) void head_kernel(
    const float* __restrict__ head_w, const float* __restrict__ head_b,
    float* __restrict__ out) {
  const int b = blockIdx.x;
  const int o = threadIdx.x;
  const float* h = g_hT + b * Hh;
  const float* wr = head_w + o * Hh;
  float acc = 0.f;
#pragma unroll 8
  for (int k = 0; k < Hh; k++) acc += h[k] * wr[k];
  out[b * HORd + o] = acc + head_b[o];
}

// ---------------------------------------------------------------------------
extern "C" void kernel_launch(void* const* d_in, const int* in_sizes, int n_in,
                              void* d_out, int out_size) {
  const float* x      = (const float*)d_in[0];
  const float* snn_w  = (const float*)d_in[1];
  const float* snn_b  = (const float*)d_in[2];
  const float* wih    = (const float*)d_in[3];
  const float* whh    = (const float*)d_in[4];
  const float* bih    = (const float*)d_in[5];
  const float* bhh    = (const float*)d_in[6];
  const float* head_w = (const float*)d_in[7];
  const float* head_b = (const float*)d_in[8];
  float* out = (float*)d_out;

  cudaFuncSetAttribute(gru_kernel,
                       cudaFuncAttributeMaxDynamicSharedMemorySize, GRU_SMEM);

  cur_gemm_kernel<<<dim3(BT / 128, Hh / 64), 256>>>(x, snn_w, snn_b);
  xcvt_kernel<<<BT * 8 / 256, 256>>>(x);
  wcvt_kernel<<<G3 * KA / 8 / 256, 256>>>(wih);
  lif_kernel<<<Bb, 256>>>();
  gx_mma_kernel<<<dim3(G3 / 64, BT / 128), 256>>>(bih);
  gru_kernel<<<Bb * 2, GRU_THREADS, GRU_SMEM>>>(whh, bhh);
  head_kernel<<<Bb, HORd>>>(head_w, head_b, out);
}